// round 1
// baseline (speedup 1.0000x reference)
#include <cuda_runtime.h>
#include <math.h>

// ---------------- problem constants ----------------
constexpr int NRES  = 768;
constexpr int NH    = 12;
constexpr long long NP = (long long)NRES * NRES;   // 589824
constexpr int DQKV  = 1152;
constexpr int DSC   = 384;
constexpr int DOUT  = 2112;
// qkv column offsets
constexpr int QS_OFF = 0, KS_OFF = 192, VS_OFF = 384, QP_OFF = 576, KP_OFF = 720, VP_OFF = 864;
// logit scales
constexpr float SSC  = 0.14433756729740643f;   // (3*16)^-0.5
constexpr float PSC  = 0.13608276348795434f;   // (3*4*4.5)^-0.5
constexpr float PBSC = 0.5773502691896258f;    // 3^-0.5

// ---------------- scratch (static device arrays; no allocation) ----------------
__device__ float g_qkv[NRES * DQKV];
__device__ float g_qp[NRES * 144];     // [i][h*12 + k*3 + c] global-frame query points
__device__ float g_kp[NRES * 144];
__device__ float g_vp[NRES * 288];     // [i][h*24 + k*3 + c]
__device__ float g_logits[(size_t)NP * 36];  // [pair][36]: cmb(12), point(12), scalar(12)
__device__ float g_edge[(size_t)NP * 36];    // softmaxed, same layout (== edge channels)
__device__ float g_attn[(size_t)NH * NP];    // [h][i][j]
__device__ float g_feats[NRES * DOUT];
__device__ float g_respts[NRES * 288];       // [i][h*24 + k*3 + c]

// ---------------- f32x2 helpers (Blackwell packed fp32) ----------------
__device__ __forceinline__ unsigned long long pk2(float x, float y) {
    unsigned long long r;
    asm("mov.b64 %0, {%1,%2};" : "=l"(r) : "f"(x), "f"(y));
    return r;
}
__device__ __forceinline__ void fma2(unsigned long long& d, unsigned long long a, unsigned long long b) {
    asm("fma.rn.f32x2 %0, %1, %2, %0;" : "+l"(d) : "l"(a), "l"(b));
}
__device__ __forceinline__ float2 un2(unsigned long long v) {
    float2 f;
    asm("mov.b64 {%0,%1}, %2;" : "=f"(f.x), "=f"(f.y) : "l"(v));
    return f;
}
__device__ __forceinline__ float gelu_exact(float x) {
    return 0.5f * x * (1.0f + erff(x * 0.70710678118654752f));
}

// ---------------- generic 64x64 tiled fp32 GEMM (row-major A[M,K] @ B[K,N] + bias) -------------
__global__ __launch_bounds__(256) void gemm_tiled(
    const float* __restrict__ A, const float* __restrict__ B, float* __restrict__ C,
    int M, int Ncols, int K, const float* __restrict__ bias)
{
    __shared__ float As[64][17];
    __shared__ float Bs[16][68];
    int tid = threadIdx.x;
    int tx = tid & 15, ty = tid >> 4;
    int bm = blockIdx.y * 64, bn = blockIdx.x * 64;
    float acc[4][4] = {};
    for (int k0 = 0; k0 < K; k0 += 16) {
        for (int idx = tid; idx < 1024; idx += 256) {
            int r = idx >> 4, c = idx & 15;
            As[r][c] = A[(size_t)(bm + r) * K + k0 + c];
        }
        for (int idx = tid; idx < 1024; idx += 256) {
            int r = idx >> 6, c = idx & 63;
            Bs[r][c] = B[(size_t)(k0 + r) * Ncols + bn + c];
        }
        __syncthreads();
#pragma unroll
        for (int kk = 0; kk < 16; kk++) {
            float a[4], b[4];
#pragma unroll
            for (int q = 0; q < 4; q++) a[q] = As[ty * 4 + q][kk];
#pragma unroll
            for (int r = 0; r < 4; r++) b[r] = Bs[kk][tx * 4 + r];
#pragma unroll
            for (int q = 0; q < 4; q++)
#pragma unroll
                for (int r = 0; r < 4; r++) acc[q][r] += a[q] * b[r];
        }
        __syncthreads();
    }
#pragma unroll
    for (int q = 0; q < 4; q++)
#pragma unroll
        for (int r = 0; r < 4; r++) {
            int row = bm + ty * 4 + q, col = bn + tx * 4 + r;
            float v = acc[q][r];
            if (bias) v += bias[col];
            C[(size_t)row * Ncols + col] = v;
        }
}

// ---------------- transform points to global frame ----------------
__global__ void k_points(const float* __restrict__ rot, const float* __restrict__ trans) {
    int i = blockIdx.x;
    int t = threadIdx.x;  // 192 threads: 48 qp, 48 kp, 96 vp
    const float* q = g_qkv + (size_t)i * DQKV;
    float p0, p1, p2;
    float* dst;
    if (t < 48) {
        int c0 = QP_OFF + t * 3;
        p0 = q[c0]; p1 = q[c0 + 1]; p2 = q[c0 + 2];
        dst = g_qp + i * 144 + t * 3;
    } else if (t < 96) {
        int u = t - 48, c0 = KP_OFF + u * 3;
        p0 = q[c0]; p1 = q[c0 + 1]; p2 = q[c0 + 2];
        dst = g_kp + i * 144 + u * 3;
    } else {
        int u = t - 96, c0 = VP_OFF + u * 3;
        p0 = q[c0]; p1 = q[c0 + 1]; p2 = q[c0 + 2];
        dst = g_vp + i * 288 + u * 3;
    }
    const float* R = rot + i * 9;
    const float* tr = trans + i * 3;
#pragma unroll
    for (int x = 0; x < 3; x++)
        dst[x] = R[x * 3 + 0] * p0 + R[x * 3 + 1] * p1 + R[x * 3 + 2] * p2 + tr[x];
}

// ---------------- fused logits: pair bias GEMV + scalar & point logits ----------------
// one warp per pair-row, 8 rows per warp
__global__ __launch_bounds__(256) void k_logits(
    const float* __restrict__ pair, const float* __restrict__ Wpb, const float* __restrict__ pw)
{
    int gwarp = (blockIdx.x * 256 + threadIdx.x) >> 5;
    int lane = threadIdx.x & 31;
    float w[4][12];
#pragma unroll
    for (int q = 0; q < 4; q++)
#pragma unroll
        for (int h = 0; h < 12; h++) w[q][h] = Wpb[(lane * 4 + q) * 12 + h];
    float sph = (lane < 12) ? log1pf(__expf(pw[lane])) : 0.f;

    size_t r0 = (size_t)gwarp * 8;
    for (int rr = 0; rr < 8; rr++) {
        size_t p = r0 + rr;
        int i = (int)(p / NRES), j = (int)(p - (size_t)i * NRES);
        float4 v = *(const float4*)(pair + p * 128 + lane * 4);
        float acc[12];
#pragma unroll
        for (int h = 0; h < 12; h++)
            acc[h] = v.x * w[0][h] + v.y * w[1][h] + v.z * w[2][h] + v.w * w[3][h];
#pragma unroll
        for (int h = 0; h < 12; h++) {
#pragma unroll
            for (int s = 16; s > 0; s >>= 1)
                acc[h] += __shfl_xor_sync(0xffffffffu, acc[h], s);
        }
        if (lane < 12) {
            int h = lane;
            const float* bi = g_qkv + (size_t)i * DQKV + QS_OFF + h * 16;
            const float* bj = g_qkv + (size_t)j * DQKV + KS_OFF + h * 16;
            float sl = 0.f;
#pragma unroll
            for (int d = 0; d < 16; d++) sl += bi[d] * bj[d];
            const float* pi = g_qp + i * 144 + h * 12;
            const float* pj = g_kp + j * 144 + h * 12;
            float pl = 0.f;
#pragma unroll
            for (int m = 0; m < 12; m++) pl += pi[m] * pj[m];
            pl *= sph;
            float* L = g_logits + p * 36;
            L[h]      = SSC * sl + PSC * pl + PBSC * acc[h];
            L[12 + h] = pl;
            L[24 + h] = sl;
        }
    }
}

// ---------------- softmax over j for all 36 channels of row i ----------------
__global__ __launch_bounds__(256) void k_softmax() {
    extern __shared__ float sbuf[];  // [36][769]
    const int PITCH = 769;
    int i = blockIdx.x;
    int tid = threadIdx.x;
    const float* src = g_logits + (size_t)i * 27648;
    for (int idx = tid; idx < 27648; idx += 256) {
        int j = idx / 36, c = idx - j * 36;
        sbuf[c * PITCH + j] = src[idx];
    }
    __syncthreads();
    int warp = tid >> 5, lane = tid & 31;
    for (int c = warp; c < 36; c += 8) {
        float* row = sbuf + c * PITCH;
        float m = -1e30f;
        for (int j = lane; j < NRES; j += 32) m = fmaxf(m, row[j]);
#pragma unroll
        for (int s = 16; s > 0; s >>= 1) m = fmaxf(m, __shfl_xor_sync(0xffffffffu, m, s));
        float sum = 0.f;
        for (int j = lane; j < NRES; j += 32) {
            float e = __expf(row[j] - m);
            row[j] = e;
            sum += e;
        }
#pragma unroll
        for (int s = 16; s > 0; s >>= 1) sum += __shfl_xor_sync(0xffffffffu, sum, s);
        float inv = 1.f / sum;
        for (int j = lane; j < NRES; j += 32) {
            float pv = row[j] * inv;
            row[j] = pv;
            if (c < 12) g_attn[(size_t)c * NP + (size_t)i * NRES + j] = pv;
        }
    }
    __syncthreads();
    float* dst = g_edge + (size_t)i * 27648;
    for (int idx = tid; idx < 27648; idx += 256) {
        int j = idx / 36, c = idx - j * 36;
        dst[idx] = sbuf[c * PITCH + j];
    }
}

// ---------------- res_pair: per i, (12x768 attn) x (768x128 pair) ----------------
__global__ __launch_bounds__(128) void k_respair(const float* __restrict__ pair) {
    int i = blockIdx.x;
    __shared__ float att[12][768];  // 36 KB
    int tid = threadIdx.x;
    for (int idx = tid; idx < 12 * 768; idx += 128) {
        int h = idx / 768, j = idx - h * 768;
        att[h][j] = g_attn[(size_t)h * NP + (size_t)i * NRES + j];
    }
    __syncthreads();
    int d4 = tid & 31, jp = tid >> 5;
    unsigned long long acc[12][2];
#pragma unroll
    for (int h = 0; h < 12; h++) { acc[h][0] = 0ull; acc[h][1] = 0ull; }
    for (int j = jp; j < NRES; j += 4) {
        float4 v = *(const float4*)(pair + ((size_t)i * NRES + j) * 128 + d4 * 4);
        unsigned long long v01 = pk2(v.x, v.y), v23 = pk2(v.z, v.w);
#pragma unroll
        for (int h = 0; h < 12; h++) {
            float a = att[h][j];
            unsigned long long ad = pk2(a, a);
            fma2(acc[h][0], ad, v01);
            fma2(acc[h][1], ad, v23);
        }
    }
    __syncthreads();
    float* red = &att[0][0];  // reuse (needs 6144 floats, has 9216)
#pragma unroll
    for (int h = 0; h < 12; h++) {
        float2 f0 = un2(acc[h][0]), f1 = un2(acc[h][1]);
        float* base = red + ((jp * 12 + h) << 7) + d4 * 4;
        base[0] = f0.x; base[1] = f0.y; base[2] = f1.x; base[3] = f1.y;
    }
    __syncthreads();
    for (int idx = tid; idx < 1536; idx += 128) {
        int h = idx >> 7, d = idx & 127;
        float s = red[((0 * 12 + h) << 7) + d] + red[((1 * 12 + h) << 7) + d]
                + red[((2 * 12 + h) << 7) + d] + red[((3 * 12 + h) << 7) + d];
        g_feats[(size_t)i * DOUT + 192 + h * 128 + d] = s;
    }
}

// ---------------- res_scalar + res_pts: per (h, 64-row i tile) ----------------
__global__ __launch_bounds__(256) void k_resv() {
    int h = blockIdx.y;
    int i0 = blockIdx.x * 64;
    __shared__ float a[64][65];
    __shared__ float v[64][40];
    int tid = threadIdx.x;
    int io = tid & 63, og = tid >> 6;  // og in 0..3, 10 outputs each
    float acc[10] = {};
    for (int j0 = 0; j0 < NRES; j0 += 64) {
        for (int idx = tid; idx < 4096; idx += 256) {
            int ii = idx >> 6, jj = idx & 63;
            a[ii][jj] = g_attn[(size_t)h * NP + (size_t)(i0 + ii) * NRES + j0 + jj];
        }
        for (int idx = tid; idx < 64 * 40; idx += 256) {
            int jj = idx / 40, o = idx - jj * 40;
            float val;
            if (o < 16) val = g_qkv[(size_t)(j0 + jj) * DQKV + VS_OFF + h * 16 + o];
            else        val = g_vp[(size_t)(j0 + jj) * 288 + h * 24 + (o - 16)];
            v[jj][o] = val;
        }
        __syncthreads();
#pragma unroll 4
        for (int jj = 0; jj < 64; jj++) {
            float av = a[io][jj];
#pragma unroll
            for (int q = 0; q < 10; q++) acc[q] += av * v[jj][og * 10 + q];
        }
        __syncthreads();
    }
#pragma unroll
    for (int q = 0; q < 10; q++) {
        int o = og * 10 + q;
        if (o < 16) g_feats[(size_t)(i0 + io) * DOUT + h * 16 + o] = acc[q];
        else        g_respts[(size_t)(i0 + io) * 288 + h * 24 + (o - 16)] = acc[q];
    }
}

// ---------------- inverse rigid transform + norms ----------------
__global__ void k_local(const float* __restrict__ rot, const float* __restrict__ trans) {
    int i = blockIdx.x;
    int t = threadIdx.x;  // 96: (h,k)
    int h = t / 8, k = t - h * 8;
    const float* R = rot + i * 9;
    const float* tr = trans + i * 3;
    float vy[3];
#pragma unroll
    for (int y = 0; y < 3; y++)
        vy[y] = g_respts[(size_t)i * 288 + h * 24 + k * 3 + y] - tr[y];
    float s = 1e-8f;
    float* fbase = g_feats + (size_t)i * DOUT;
#pragma unroll
    for (int x = 0; x < 3; x++) {
        float l = R[0 * 3 + x] * vy[0] + R[1 * 3 + x] * vy[1] + R[2 * 3 + x] * vy[2];
        fbase[1728 + h * 24 + k * 3 + x] = l;
        s += l * l;
    }
    fbase[2016 + h * 8 + k] = sqrtf(s);
}

// ---------------- pair MLP: edge(36) -> gelu(128) -> out(128), persistent CTAs ----------------
constexpr int MLP_SMEM = (36 * 128 + 128 * 128 + 128 * 37 + 128 * 128) * 4;  // 168448 B

__global__ __launch_bounds__(256, 1) void k_pairmlp(
    const float* __restrict__ Wp1, const float* __restrict__ bp1,
    const float* __restrict__ Wp2, const float* __restrict__ bp2,
    float* __restrict__ out)
{
    extern __shared__ float sm[];
    float* sW1 = sm;                       // 36*128
    float* sW2 = sW1 + 36 * 128;           // 128*128
    float* sE  = sW2 + 128 * 128;          // 128*37 (padded)
    float* sH  = sE  + 128 * 37;           // 128*128
    int tid = threadIdx.x;
    for (int idx = tid; idx < 36 * 128; idx += 256) sW1[idx] = Wp1[idx];
    for (int idx = tid; idx < 128 * 128; idx += 256) sW2[idx] = Wp2[idx];
    int tx = tid & 15, ty = tid >> 4;
    int c0 = tx * 8, p0 = ty * 8;
    float b1[8], b2[8];
#pragma unroll
    for (int r = 0; r < 8; r++) { b1[r] = bp1[c0 + r]; b2[r] = bp2[c0 + r]; }
    __syncthreads();

    int ntiles = (int)(NP / 128);  // 4608
    for (int t = blockIdx.x; t < ntiles; t += gridDim.x) {
        const float* src = g_edge + (size_t)t * 128 * 36;
        for (int idx = tid; idx < 128 * 36; idx += 256) {
            int p = idx / 36, e = idx - p * 36;
            sE[p * 37 + e] = src[idx];
        }
        __syncthreads();

        // stage A: hidden = gelu(edge @ W1 + b1)
        unsigned long long a2[8][4];
#pragma unroll
        for (int q = 0; q < 8; q++)
#pragma unroll
            for (int r = 0; r < 4; r++) a2[q][r] = pk2(b1[2 * r], b1[2 * r + 1]);
#pragma unroll 4
        for (int e = 0; e < 36; e++) {
            float4 w0 = *(const float4*)&sW1[e * 128 + c0];
            float4 w1 = *(const float4*)&sW1[e * 128 + c0 + 4];
            unsigned long long W0 = pk2(w0.x, w0.y), W1v = pk2(w0.z, w0.w);
            unsigned long long W2v = pk2(w1.x, w1.y), W3 = pk2(w1.z, w1.w);
#pragma unroll
            for (int q = 0; q < 8; q++) {
                float a = sE[(p0 + q) * 37 + e];
                unsigned long long ad = pk2(a, a);
                fma2(a2[q][0], ad, W0);
                fma2(a2[q][1], ad, W1v);
                fma2(a2[q][2], ad, W2v);
                fma2(a2[q][3], ad, W3);
            }
        }
#pragma unroll
        for (int q = 0; q < 8; q++) {
            float hv[8];
#pragma unroll
            for (int r = 0; r < 4; r++) {
                float2 f = un2(a2[q][r]);
                hv[2 * r] = gelu_exact(f.x);
                hv[2 * r + 1] = gelu_exact(f.y);
            }
            *(float4*)&sH[(p0 + q) * 128 + c0]     = make_float4(hv[0], hv[1], hv[2], hv[3]);
            *(float4*)&sH[(p0 + q) * 128 + c0 + 4] = make_float4(hv[4], hv[5], hv[6], hv[7]);
        }
        __syncthreads();

        // stage B: out = hidden @ W2 + b2
        unsigned long long o2[8][4];
#pragma unroll
        for (int q = 0; q < 8; q++)
#pragma unroll
            for (int r = 0; r < 4; r++) o2[q][r] = pk2(b2[2 * r], b2[2 * r + 1]);
#pragma unroll 4
        for (int k = 0; k < 128; k++) {
            float4 w0 = *(const float4*)&sW2[k * 128 + c0];
            float4 w1 = *(const float4*)&sW2[k * 128 + c0 + 4];
            unsigned long long W0 = pk2(w0.x, w0.y), W1v = pk2(w0.z, w0.w);
            unsigned long long W2v = pk2(w1.x, w1.y), W3 = pk2(w1.z, w1.w);
#pragma unroll
            for (int q = 0; q < 8; q++) {
                float hval = sH[(p0 + q) * 128 + k];
                unsigned long long hd = pk2(hval, hval);
                fma2(o2[q][0], hd, W0);
                fma2(o2[q][1], hd, W1v);
                fma2(o2[q][2], hd, W2v);
                fma2(o2[q][3], hd, W3);
            }
        }
        float* dst = out + (size_t)t * 128 * 128;
#pragma unroll
        for (int q = 0; q < 8; q++) {
            float2 f0 = un2(o2[q][0]), f1 = un2(o2[q][1]);
            float2 f2 = un2(o2[q][2]), f3 = un2(o2[q][3]);
            *(float4*)&dst[(size_t)(p0 + q) * 128 + c0]     = make_float4(f0.x, f0.y, f1.x, f1.y);
            *(float4*)&dst[(size_t)(p0 + q) * 128 + c0 + 4] = make_float4(f2.x, f2.y, f3.x, f3.y);
        }
        // no extra sync needed: next loop's sE load doesn't touch sH/sW2,
        // and the post-load __syncthreads orders stage-A sH writes after these reads.
    }
}

// ---------------- host launcher ----------------
extern "C" void kernel_launch(void* const* d_in, const int* in_sizes, int n_in,
                              void* d_out, int out_size) {
    const float* scalar = (const float*)d_in[0];
    const float* pair   = (const float*)d_in[1];
    const float* rot    = (const float*)d_in[2];
    const float* trans  = (const float*)d_in[3];
    // d_in[4] = mask (all true for this problem; masking is a no-op)
    const float* Wqkv = (const float*)d_in[5];
    const float* Wpb  = (const float*)d_in[6];
    const float* pw   = (const float*)d_in[7];
    const float* Wout = (const float*)d_in[8];
    const float* bout = (const float*)d_in[9];
    const float* Wp1  = (const float*)d_in[10];
    const float* bp1  = (const float*)d_in[11];
    const float* Wp2  = (const float*)d_in[12];
    const float* bp2  = (const float*)d_in[13];
    float* out = (float*)d_out;

    static bool attr_done = false;
    // idempotent + cheap; safe to repeat every call (no state dependence on call count)
    cudaFuncSetAttribute(k_softmax, cudaFuncAttributeMaxDynamicSharedMemorySize, 36 * 769 * 4);
    cudaFuncSetAttribute(k_pairmlp, cudaFuncAttributeMaxDynamicSharedMemorySize, MLP_SMEM);
    (void)attr_done;

    float* g_qkv_p;   cudaGetSymbolAddress((void**)&g_qkv_p, g_qkv);  // not strictly needed; kernels use symbols

    // 1) qkv projection: (768x384) @ (384x1152)
    gemm_tiled<<<dim3(1152 / 64, NRES / 64), 256>>>(scalar, Wqkv, g_qkv_p, NRES, DQKV, DSC, nullptr);
    // 2) points to global frame
    k_points<<<NRES, 192>>>(rot, trans);
    // 3) fused logits (pair bias + scalar + point)
    k_logits<<<(int)(NP / 64), 256>>>(pair, Wpb, pw);
    // 4) 36-channel softmax per row i
    k_softmax<<<NRES, 256, 36 * 769 * 4>>>();
    // 5) res_pair
    k_respair<<<NRES, 128>>>(pair);
    // 6) res_scalar + res_pts
    k_resv<<<dim3(NRES / 64, NH), 256>>>();
    // 7) local frame + norms
    k_local<<<NRES, 96>>>(rot, trans);
    // 8) scalar_out = feats @ Wout + bout -> d_out[0 : 768*384)
    {
        float* g_feats_p; cudaGetSymbolAddress((void**)&g_feats_p, g_feats);
        gemm_tiled<<<dim3(DSC / 64, NRES / 64), 256>>>(g_feats_p, Wout, out, NRES, DSC, DOUT, bout);
    }
    // 9) pair MLP -> d_out[768*384 : ...)
    k_pairmlp<<<152, 256, MLP_SMEM>>>(Wp1, bp1, Wp2, bp2, out + NRES * DSC);
}

// round 2
// speedup vs baseline: 1.7598x; 1.7598x over previous
#include <cuda_runtime.h>
#include <cuda_bf16.h>
#include <math.h>
#include <stdint.h>

// ---------------- problem constants ----------------
constexpr int NRES  = 768;
constexpr int NH    = 12;
constexpr long long NP = (long long)NRES * NRES;   // 589824
constexpr int DQKV  = 1152;
constexpr int DSC   = 384;
constexpr int DOUT  = 2112;
constexpr int QS_OFF = 0, KS_OFF = 192, VS_OFF = 384, QP_OFF = 576, KP_OFF = 720, VP_OFF = 864;
constexpr float SSC  = 0.14433756729740643f;   // (3*16)^-0.5
constexpr float PSC  = 0.13608276348795434f;   // (3*4*4.5)^-0.5
constexpr float PBSC = 0.5773502691896258f;    // 3^-0.5

// ---------------- scratch ----------------
__device__ float g_qkv[NRES * DQKV];
__device__ float g_qp[NRES * 144];
__device__ float g_kp[NRES * 144];
__device__ float g_vp[NRES * 288];
__device__ float g_logits[(size_t)NP * 36];  // [i][c][j] channel-major: c: 0-11 cmb/pb, 12-23 point, 24-35 scalar
__device__ float g_edge[(size_t)NP * 36];    // [i][c][j] softmaxed
__device__ float g_attn[(size_t)NH * NP];    // [h][i][j]
__device__ float g_feats[NRES * DOUT];
__device__ float g_respts[NRES * 288];

__device__ __forceinline__ float gelu_exact(float x) {
    return 0.5f * x * (1.0f + erff(x * 0.70710678118654752f));
}

// ---------------- generic 64x64 tiled fp32 GEMM ----------------
__global__ __launch_bounds__(256) void gemm_tiled(
    const float* __restrict__ A, const float* __restrict__ B, float* __restrict__ C,
    int M, int Ncols, int K, const float* __restrict__ bias)
{
    __shared__ float As[64][17];
    __shared__ float Bs[16][68];
    int tid = threadIdx.x;
    int tx = tid & 15, ty = tid >> 4;
    int bm = blockIdx.y * 64, bn = blockIdx.x * 64;
    float acc[4][4] = {};
    for (int k0 = 0; k0 < K; k0 += 16) {
        for (int idx = tid; idx < 1024; idx += 256) {
            int r = idx >> 4, c = idx & 15;
            As[r][c] = A[(size_t)(bm + r) * K + k0 + c];
        }
        for (int idx = tid; idx < 1024; idx += 256) {
            int r = idx >> 6, c = idx & 63;
            Bs[r][c] = B[(size_t)(k0 + r) * Ncols + bn + c];
        }
        __syncthreads();
#pragma unroll
        for (int kk = 0; kk < 16; kk++) {
            float a[4], b[4];
#pragma unroll
            for (int q = 0; q < 4; q++) a[q] = As[ty * 4 + q][kk];
#pragma unroll
            for (int r = 0; r < 4; r++) b[r] = Bs[kk][tx * 4 + r];
#pragma unroll
            for (int q = 0; q < 4; q++)
#pragma unroll
                for (int r = 0; r < 4; r++) acc[q][r] += a[q] * b[r];
        }
        __syncthreads();
    }
#pragma unroll
    for (int q = 0; q < 4; q++)
#pragma unroll
        for (int r = 0; r < 4; r++) {
            int row = bm + ty * 4 + q, col = bn + tx * 4 + r;
            float v = acc[q][r];
            if (bias) v += bias[col];
            C[(size_t)row * Ncols + col] = v;
        }
}

// ---------------- points to global frame ----------------
__global__ void k_points(const float* __restrict__ rot, const float* __restrict__ trans) {
    int i = blockIdx.x;
    int t = threadIdx.x;
    const float* q = g_qkv + (size_t)i * DQKV;
    float p0, p1, p2;
    float* dst;
    if (t < 48) {
        int c0 = QP_OFF + t * 3;
        p0 = q[c0]; p1 = q[c0 + 1]; p2 = q[c0 + 2];
        dst = g_qp + i * 144 + t * 3;
    } else if (t < 96) {
        int u = t - 48, c0 = KP_OFF + u * 3;
        p0 = q[c0]; p1 = q[c0 + 1]; p2 = q[c0 + 2];
        dst = g_kp + i * 144 + u * 3;
    } else {
        int u = t - 96, c0 = VP_OFF + u * 3;
        p0 = q[c0]; p1 = q[c0 + 1]; p2 = q[c0 + 2];
        dst = g_vp + i * 288 + u * 3;
    }
    const float* R = rot + i * 9;
    const float* tr = trans + i * 3;
#pragma unroll
    for (int x = 0; x < 3; x++)
        dst[x] = R[x * 3 + 0] * p0 + R[x * 3 + 1] * p1 + R[x * 3 + 2] * p2 + tr[x];
}

// ---------------- pair bias GEMM: pb[i,j,h] -> g_logits channel h ----------------
__global__ __launch_bounds__(256) void k_pairbias(
    const float* __restrict__ pair, const float* __restrict__ Wpb)
{
    int i = blockIdx.x / 3;
    int j0 = (blockIdx.x % 3) * 256;
    __shared__ float sP[256][33];
    __shared__ float sW[32][12];
    int tid = threadIdx.x;
    float acc[12] = {};
    const float* prow = pair + ((size_t)i * NRES + j0) * 128;
    for (int k0 = 0; k0 < 128; k0 += 32) {
        for (int idx = tid; idx < 256 * 32; idx += 256) {
            int r = idx >> 5, c = idx & 31;
            sP[r][c] = prow[(size_t)r * 128 + k0 + c];
        }
        for (int idx = tid; idx < 32 * 12; idx += 256)
            sW[idx / 12][idx % 12] = Wpb[(k0 + idx / 12) * 12 + idx % 12];
        __syncthreads();
#pragma unroll 8
        for (int k = 0; k < 32; k++) {
            float a = sP[tid][k];
#pragma unroll
            for (int h = 0; h < 12; h++) acc[h] += a * sW[k][h];
        }
        __syncthreads();
    }
    size_t base = ((size_t)i * 36) * NRES + j0 + tid;
#pragma unroll
    for (int h = 0; h < 12; h++) g_logits[base + (size_t)h * NRES] = acc[h];
}

// ---------------- QK logits per head, 64x64 tiles; combine with pb ----------------
__global__ __launch_bounds__(256) void k_qk(const float* __restrict__ pw) {
    int h = blockIdx.z;
    int i0 = blockIdx.y * 64, j0 = blockIdx.x * 64;
    __shared__ float sq[64][17], sk[64][17], sqp[64][13], skp[64][13];
    int tid = threadIdx.x;
    for (int idx = tid; idx < 1024; idx += 256) {
        int r = idx >> 4, c = idx & 15;
        sq[r][c] = g_qkv[(size_t)(i0 + r) * DQKV + QS_OFF + h * 16 + c];
        sk[r][c] = g_qkv[(size_t)(j0 + r) * DQKV + KS_OFF + h * 16 + c];
    }
    for (int idx = tid; idx < 768; idx += 256) {
        int r = idx / 12, c = idx - r * 12;
        sqp[r][c] = g_qp[(i0 + r) * 144 + h * 12 + c];
        skp[r][c] = g_kp[(j0 + r) * 144 + h * 12 + c];
    }
    float sph = log1pf(__expf(pw[h]));
    __syncthreads();
    int tx = tid & 15, ty = tid >> 4;
    float sl[4][4] = {}, pl[4][4] = {};
#pragma unroll
    for (int k = 0; k < 16; k++) {
        float a[4], b[4];
#pragma unroll
        for (int q = 0; q < 4; q++) a[q] = sq[ty * 4 + q][k];
#pragma unroll
        for (int r = 0; r < 4; r++) b[r] = sk[tx * 4 + r][k];
#pragma unroll
        for (int q = 0; q < 4; q++)
#pragma unroll
            for (int r = 0; r < 4; r++) sl[q][r] += a[q] * b[r];
    }
#pragma unroll
    for (int k = 0; k < 12; k++) {
        float a[4], b[4];
#pragma unroll
        for (int q = 0; q < 4; q++) a[q] = sqp[ty * 4 + q][k];
#pragma unroll
        for (int r = 0; r < 4; r++) b[r] = skp[tx * 4 + r][k];
#pragma unroll
        for (int q = 0; q < 4; q++)
#pragma unroll
            for (int r = 0; r < 4; r++) pl[q][r] += a[q] * b[r];
    }
#pragma unroll
    for (int q = 0; q < 4; q++) {
        int i = i0 + ty * 4 + q;
        size_t bc = ((size_t)i * 36 + h) * NRES;
#pragma unroll
        for (int r = 0; r < 4; r++) {
            int j = j0 + tx * 4 + r;
            float plv = pl[q][r] * sph;
            float pb = g_logits[bc + j];
            g_logits[bc + j] = SSC * sl[q][r] + PSC * plv + PBSC * pb;
            g_logits[bc + (size_t)12 * NRES + j] = plv;
            g_logits[bc + (size_t)24 * NRES + j] = sl[q][r];
        }
    }
}

// ---------------- softmax over j per (i, channel), register-resident ----------------
__global__ __launch_bounds__(256) void k_softmax2() {
    int i = blockIdx.x;
    int warp = threadIdx.x >> 5, lane = threadIdx.x & 31;
    for (int c = warp; c < 36; c += 8) {
        const float* src = g_logits + ((size_t)i * 36 + c) * NRES;
        float v[24];
        float m = -1e30f;
#pragma unroll
        for (int t = 0; t < 24; t++) { v[t] = src[lane + t * 32]; m = fmaxf(m, v[t]); }
#pragma unroll
        for (int s = 16; s > 0; s >>= 1) m = fmaxf(m, __shfl_xor_sync(0xffffffffu, m, s));
        float sum = 0.f;
#pragma unroll
        for (int t = 0; t < 24; t++) { v[t] = __expf(v[t] - m); sum += v[t]; }
#pragma unroll
        for (int s = 16; s > 0; s >>= 1) sum += __shfl_xor_sync(0xffffffffu, sum, s);
        float inv = 1.f / sum;
        float* dst = g_edge + ((size_t)i * 36 + c) * NRES;
#pragma unroll
        for (int t = 0; t < 24; t++) dst[lane + t * 32] = v[t] * inv;
        if (c < 12) {
            float* ad = g_attn + (size_t)c * NP + (size_t)i * NRES;
#pragma unroll
            for (int t = 0; t < 24; t++) ad[lane + t * 32] = v[t] * inv;
        }
    }
}

// ---------------- res_pair: per i, (12x768 attn) x (768x128 pair) ----------------
__global__ __launch_bounds__(128) void k_respair(const float* __restrict__ pair) {
    int i = blockIdx.x;
    __shared__ float att[12][768];  // 36 KB (reused for reduction)
    int tid = threadIdx.x;
    for (int idx = tid; idx < 12 * 768; idx += 128) {
        int h = idx / 768, j = idx - h * 768;
        att[h][j] = g_attn[(size_t)h * NP + (size_t)i * NRES + j];
    }
    __syncthreads();
    int d4 = tid & 31, jp = tid >> 5;
    float acc[12][4] = {};
    for (int j = jp; j < NRES; j += 4) {
        float4 v = *(const float4*)(pair + ((size_t)i * NRES + j) * 128 + d4 * 4);
#pragma unroll
        for (int h = 0; h < 12; h++) {
            float a = att[h][j];
            acc[h][0] += a * v.x; acc[h][1] += a * v.y;
            acc[h][2] += a * v.z; acc[h][3] += a * v.w;
        }
    }
    __syncthreads();
    float* red = &att[0][0];  // needs 6144 floats, has 9216
#pragma unroll
    for (int h = 0; h < 12; h++) {
        float* base = red + ((jp * 12 + h) << 7) + d4 * 4;
        base[0] = acc[h][0]; base[1] = acc[h][1]; base[2] = acc[h][2]; base[3] = acc[h][3];
    }
    __syncthreads();
    for (int idx = tid; idx < 1536; idx += 128) {
        int h = idx >> 7, d = idx & 127;
        float s = red[((0 * 12 + h) << 7) + d] + red[((1 * 12 + h) << 7) + d]
                + red[((2 * 12 + h) << 7) + d] + red[((3 * 12 + h) << 7) + d];
        g_feats[(size_t)i * DOUT + 192 + h * 128 + d] = s;
    }
}

// ---------------- res_scalar + res_pts ----------------
__global__ __launch_bounds__(256) void k_resv() {
    int h = blockIdx.y;
    int i0 = blockIdx.x * 64;
    __shared__ float a[64][65];
    __shared__ float v[64][40];
    int tid = threadIdx.x;
    int io = tid & 63, og = tid >> 6;
    float acc[10] = {};
    for (int j0 = 0; j0 < NRES; j0 += 64) {
        for (int idx = tid; idx < 4096; idx += 256) {
            int ii = idx >> 6, jj = idx & 63;
            a[ii][jj] = g_attn[(size_t)h * NP + (size_t)(i0 + ii) * NRES + j0 + jj];
        }
        for (int idx = tid; idx < 64 * 40; idx += 256) {
            int jj = idx / 40, o = idx - jj * 40;
            float val;
            if (o < 16) val = g_qkv[(size_t)(j0 + jj) * DQKV + VS_OFF + h * 16 + o];
            else        val = g_vp[(size_t)(j0 + jj) * 288 + h * 24 + (o - 16)];
            v[jj][o] = val;
        }
        __syncthreads();
#pragma unroll 4
        for (int jj = 0; jj < 64; jj++) {
            float av = a[io][jj];
#pragma unroll
            for (int q = 0; q < 10; q++) acc[q] += av * v[jj][og * 10 + q];
        }
        __syncthreads();
    }
#pragma unroll
    for (int q = 0; q < 10; q++) {
        int o = og * 10 + q;
        if (o < 16) g_feats[(size_t)(i0 + io) * DOUT + h * 16 + o] = acc[q];
        else        g_respts[(size_t)(i0 + io) * 288 + h * 24 + (o - 16)] = acc[q];
    }
}

// ---------------- inverse rigid + norms ----------------
__global__ void k_local(const float* __restrict__ rot, const float* __restrict__ trans) {
    int i = blockIdx.x;
    int t = threadIdx.x;  // 96: (h,k)
    int h = t / 8, k = t - h * 8;
    const float* R = rot + i * 9;
    const float* tr = trans + i * 3;
    float vy[3];
#pragma unroll
    for (int y = 0; y < 3; y++)
        vy[y] = g_respts[(size_t)i * 288 + h * 24 + k * 3 + y] - tr[y];
    float s = 1e-8f;
    float* fbase = g_feats + (size_t)i * DOUT;
#pragma unroll
    for (int x = 0; x < 3; x++) {
        float l = R[0 * 3 + x] * vy[0] + R[1 * 3 + x] * vy[1] + R[2 * 3 + x] * vy[2];
        fbase[1728 + h * 24 + k * 3 + x] = l;
        s += l * l;
    }
    fbase[2016 + h * 8 + k] = sqrtf(s);
}

// ================= pair MLP on tensor cores (bf16 2-split, 3-pass) =================
constexpr int W1P = 136, W2P = 136, EP = 56, HP = 136;   // row pitches in bf16 elements
constexpr int OFF_W1H = 0;
constexpr int OFF_W1L = OFF_W1H + 48 * W1P * 2;
constexpr int OFF_W2H = OFF_W1L + 48 * W1P * 2;
constexpr int OFF_W2L = OFF_W2H + 128 * W2P * 2;
constexpr int OFF_EH  = OFF_W2L + 128 * W2P * 2;
constexpr int OFF_EL  = OFF_EH + 128 * EP * 2;
constexpr int OFF_HH  = OFF_EL + 128 * EP * 2;
constexpr int OFF_HL  = OFF_HH + 128 * HP * 2;
constexpr int OFF_B1  = OFF_HL + 128 * HP * 2;
constexpr int OFF_B2  = OFF_B1 + 512;
constexpr int MLP_SMEM = OFF_B2 + 512;   // 195072 bytes

__device__ __forceinline__ uint32_t s2u(const void* p) {
    uint32_t a;
    asm("{.reg .u64 t; cvta.to.shared.u64 t, %1; cvt.u32.u64 %0, t;}" : "=r"(a) : "l"(p));
    return a;
}
__device__ __forceinline__ void ldm4(uint32_t r[4], uint32_t a) {
    asm volatile("ldmatrix.sync.aligned.m8n8.x4.shared.b16 {%0,%1,%2,%3},[%4];"
                 : "=r"(r[0]), "=r"(r[1]), "=r"(r[2]), "=r"(r[3]) : "r"(a));
}
__device__ __forceinline__ void ldm4t(uint32_t r[4], uint32_t a) {
    asm volatile("ldmatrix.sync.aligned.m8n8.x4.trans.shared.b16 {%0,%1,%2,%3},[%4];"
                 : "=r"(r[0]), "=r"(r[1]), "=r"(r[2]), "=r"(r[3]) : "r"(a));
}
__device__ __forceinline__ void mma_bf16(float c[4], const uint32_t a[4], uint32_t b0, uint32_t b1) {
    asm volatile(
        "mma.sync.aligned.m16n8k16.row.col.f32.bf16.bf16.f32 "
        "{%0,%1,%2,%3},{%4,%5,%6,%7},{%8,%9},{%0,%1,%2,%3};"
        : "+f"(c[0]), "+f"(c[1]), "+f"(c[2]), "+f"(c[3])
        : "r"(a[0]), "r"(a[1]), "r"(a[2]), "r"(a[3]), "r"(b0), "r"(b1));
}
__device__ __forceinline__ void split2(float x, float y, uint32_t& hi, uint32_t& lo) {
    __nv_bfloat16 hx = __float2bfloat16_rn(x), hy = __float2bfloat16_rn(y);
    float rx = x - __bfloat162float(hx), ry = y - __bfloat162float(hy);
    __nv_bfloat162 th = __halves2bfloat162(hx, hy);
    __nv_bfloat162 tl = __floats2bfloat162_rn(rx, ry);
    hi = *reinterpret_cast<uint32_t*>(&th);
    lo = *reinterpret_cast<uint32_t*>(&tl);
}

__global__ __launch_bounds__(256, 1) void k_pairmlp_mma(
    const float* __restrict__ Wp1, const float* __restrict__ bp1,
    const float* __restrict__ Wp2, const float* __restrict__ bp2,
    float* __restrict__ out)
{
    extern __shared__ char sm[];
    uint32_t sb = s2u(sm);
    int tid = threadIdx.x, lane = tid & 31, w = tid >> 5;

    // load & split weights (once)
    for (int idx = tid; idx < 48 * 128; idx += 256) {
        int k = idx >> 7, n = idx & 127;
        float v = (k < 36) ? Wp1[k * 128 + n] : 0.f;
        __nv_bfloat16 h = __float2bfloat16_rn(v);
        ((__nv_bfloat16*)(sm + OFF_W1H))[k * W1P + n] = h;
        ((__nv_bfloat16*)(sm + OFF_W1L))[k * W1P + n] = __float2bfloat16_rn(v - __bfloat162float(h));
    }
    for (int idx = tid; idx < 128 * 128; idx += 256) {
        int k = idx >> 7, n = idx & 127;
        float v = Wp2[idx];
        __nv_bfloat16 h = __float2bfloat16_rn(v);
        ((__nv_bfloat16*)(sm + OFF_W2H))[k * W2P + n] = h;
        ((__nv_bfloat16*)(sm + OFF_W2L))[k * W2P + n] = __float2bfloat16_rn(v - __bfloat162float(h));
    }
    if (tid < 128) {
        ((float*)(sm + OFF_B1))[tid] = bp1[tid];
        ((float*)(sm + OFF_B2))[tid] = bp2[tid];
    }
    for (int idx = tid; idx < 128 * 12; idx += 256) {   // zero E pad cols 36..47
        int r = idx / 12, c = 36 + idx % 12;
        ((__nv_bfloat16*)(sm + OFF_EH))[r * EP + c] = __float2bfloat16_rn(0.f);
        ((__nv_bfloat16*)(sm + OFF_EL))[r * EP + c] = __float2bfloat16_rn(0.f);
    }

    // per-lane ldmatrix offsets
    uint32_t aAoffE = (lane & 15) * (EP * 2) + (lane >> 4) * 16;
    uint32_t aAoffH = (lane & 15) * (HP * 2) + (lane >> 4) * 16;
    int brow = (lane & 7) + ((lane >> 3) & 1) * 8, bc8 = (lane >> 4) * 8;
    uint32_t aBoff1 = brow * (W1P * 2) + bc8 * 2;
    uint32_t aBoff2 = brow * (W2P * 2) + bc8 * 2;

    const float* b1 = (const float*)(sm + OFF_B1);
    const float* b2 = (const float*)(sm + OFF_B2);
    int r0 = w * 16;

    for (int t = blockIdx.x; t < 4608; t += gridDim.x) {
        __syncthreads();   // protects sE against warps still in previous tile's layer 1
        {
            int i = t / 6, j0 = (t % 6) * 128;
            const float* src = g_edge + ((size_t)i * 36) * NRES + j0;
            for (int idx = tid; idx < 36 * 128; idx += 256) {
                int c = idx >> 7, jj = idx & 127;
                float v = src[(size_t)c * NRES + jj];
                __nv_bfloat16 h = __float2bfloat16_rn(v);
                ((__nv_bfloat16*)(sm + OFF_EH))[jj * EP + c] = h;
                ((__nv_bfloat16*)(sm + OFF_EL))[jj * EP + c] =
                    __float2bfloat16_rn(v - __bfloat162float(h));
            }
        }
        __syncthreads();

        // ---- layer 1: H = gelu(E @ W1 + b1), K=48 ----
        float acc[16][4];
#pragma unroll
        for (int n = 0; n < 16; n++) {
            float2 bb = *(const float2*)&b1[n * 8 + (lane & 3) * 2];
            acc[n][0] = bb.x; acc[n][1] = bb.y; acc[n][2] = bb.x; acc[n][3] = bb.y;
        }
#pragma unroll
        for (int ks = 0; ks < 3; ks++) {
            uint32_t ah[4], al[4];
            ldm4(ah, sb + OFF_EH + r0 * (EP * 2) + aAoffE + ks * 32);
            ldm4(al, sb + OFF_EL + r0 * (EP * 2) + aAoffE + ks * 32);
#pragma unroll
            for (int n = 0; n < 8; n++) {
                uint32_t bh[4], bl[4];
                ldm4t(bh, sb + OFF_W1H + ks * 16 * (W1P * 2) + aBoff1 + n * 32);
                ldm4t(bl, sb + OFF_W1L + ks * 16 * (W1P * 2) + aBoff1 + n * 32);
                mma_bf16(acc[2 * n], ah, bh[0], bh[1]);
                mma_bf16(acc[2 * n], ah, bl[0], bl[1]);
                mma_bf16(acc[2 * n], al, bh[0], bh[1]);
                mma_bf16(acc[2 * n + 1], ah, bh[2], bh[3]);
                mma_bf16(acc[2 * n + 1], ah, bl[2], bl[3]);
                mma_bf16(acc[2 * n + 1], al, bh[2], bh[3]);
            }
        }
        {
            int rlo = r0 + (lane >> 2);
#pragma unroll
            for (int n = 0; n < 16; n++) {
                int c = n * 8 + (lane & 3) * 2;
                float g0 = gelu_exact(acc[n][0]), g1 = gelu_exact(acc[n][1]);
                float g2 = gelu_exact(acc[n][2]), g3 = gelu_exact(acc[n][3]);
                uint32_t h01, l01, h23, l23;
                split2(g0, g1, h01, l01);
                split2(g2, g3, h23, l23);
                *(uint32_t*)(sm + OFF_HH + rlo * (HP * 2) + c * 2) = h01;
                *(uint32_t*)(sm + OFF_HL + rlo * (HP * 2) + c * 2) = l01;
                *(uint32_t*)(sm + OFF_HH + (rlo + 8) * (HP * 2) + c * 2) = h23;
                *(uint32_t*)(sm + OFF_HL + (rlo + 8) * (HP * 2) + c * 2) = l23;
            }
        }
        __syncthreads();

        // ---- layer 2: out = H @ W2 + b2, K=128 ----
#pragma unroll
        for (int n = 0; n < 16; n++) {
            float2 bb = *(const float2*)&b2[n * 8 + (lane & 3) * 2];
            acc[n][0] = bb.x; acc[n][1] = bb.y; acc[n][2] = bb.x; acc[n][3] = bb.y;
        }
#pragma unroll
        for (int ks = 0; ks < 8; ks++) {
            uint32_t ah[4], al[4];
            ldm4(ah, sb + OFF_HH + r0 * (HP * 2) + aAoffH + ks * 32);
            ldm4(al, sb + OFF_HL + r0 * (HP * 2) + aAoffH + ks * 32);
#pragma unroll
            for (int n = 0; n < 8; n++) {
                uint32_t bh[4], bl[4];
                ldm4t(bh, sb + OFF_W2H + ks * 16 * (W2P * 2) + aBoff2 + n * 32);
                ldm4t(bl, sb + OFF_W2L + ks * 16 * (W2P * 2) + aBoff2 + n * 32);
                mma_bf16(acc[2 * n], ah, bh[0], bh[1]);
                mma_bf16(acc[2 * n], ah, bl[0], bl[1]);
                mma_bf16(acc[2 * n], al, bh[0], bh[1]);
                mma_bf16(acc[2 * n + 1], ah, bh[2], bh[3]);
                mma_bf16(acc[2 * n + 1], ah, bl[2], bl[3]);
                mma_bf16(acc[2 * n + 1], al, bh[2], bh[3]);
            }
        }
        {
            float* dst = out + (size_t)t * 128 * 128;
            int rlo = r0 + (lane >> 2);
#pragma unroll
            for (int n = 0; n < 16; n++) {
                int c = n * 8 + (lane & 3) * 2;
                *(float2*)&dst[(size_t)rlo * 128 + c] = make_float2(acc[n][0], acc[n][1]);
                *(float2*)&dst[(size_t)(rlo + 8) * 128 + c] = make_float2(acc[n][2], acc[n][3]);
            }
        }
    }
}

// ---------------- host launcher ----------------
extern "C" void kernel_launch(void* const* d_in, const int* in_sizes, int n_in,
                              void* d_out, int out_size) {
    const float* scalar = (const float*)d_in[0];
    const float* pair   = (const float*)d_in[1];
    const float* rot    = (const float*)d_in[2];
    const float* trans  = (const float*)d_in[3];
    // d_in[4] = mask (all true; no-op)
    const float* Wqkv = (const float*)d_in[5];
    const float* Wpb  = (const float*)d_in[6];
    const float* pw   = (const float*)d_in[7];
    const float* Wout = (const float*)d_in[8];
    const float* bout = (const float*)d_in[9];
    const float* Wp1  = (const float*)d_in[10];
    const float* bp1  = (const float*)d_in[11];
    const float* Wp2  = (const float*)d_in[12];
    const float* bp2  = (const float*)d_in[13];
    float* out = (float*)d_out;

    cudaFuncSetAttribute(k_pairmlp_mma, cudaFuncAttributeMaxDynamicSharedMemorySize, MLP_SMEM);

    float* g_qkv_p;   cudaGetSymbolAddress((void**)&g_qkv_p, g_qkv);
    float* g_feats_p; cudaGetSymbolAddress((void**)&g_feats_p, g_feats);

    // 1) qkv projection
    gemm_tiled<<<dim3(DQKV / 64, NRES / 64), 256>>>(scalar, Wqkv, g_qkv_p, NRES, DQKV, DSC, nullptr);
    // 2) points to global frame
    k_points<<<NRES, 192>>>(rot, trans);
    // 3) pair bias GEMM -> g_logits channels 0..11
    k_pairbias<<<NRES * 3, 256>>>(pair, Wpb);
    // 4) QK scalar/point logits + combine
    k_qk<<<dim3(NRES / 64, NRES / 64, NH), 256>>>(pw);
    // 5) softmax over j per (i, channel)
    k_softmax2<<<NRES, 256>>>();
    // 6) res_pair
    k_respair<<<NRES, 128>>>(pair);
    // 7) res_scalar + res_pts
    k_resv<<<dim3(NRES / 64, NH), 256>>>();
    // 8) local frame + norms
    k_local<<<NRES, 96>>>(rot, trans);
    // 9) scalar_out
    gemm_tiled<<<dim3(DSC / 64, NRES / 64), 256>>>(g_feats_p, Wout, out, NRES, DSC, DOUT, bout);
    // 10) pair MLP (tensor cores)
    k_pairmlp_mma<<<152, 256, MLP_SMEM>>>(Wp1, bp1, Wp2, bp2, out + NRES * DSC);
}

// round 3
// speedup vs baseline: 2.3313x; 1.3247x over previous
#include <cuda_runtime.h>
#include <cuda_bf16.h>
#include <math.h>
#include <stdint.h>

// ---------------- problem constants ----------------
constexpr int NRES  = 768;
constexpr int NH    = 12;
constexpr long long NP = (long long)NRES * NRES;   // 589824
constexpr int DQKV  = 1152;
constexpr int DSC   = 384;
constexpr int DOUT  = 2112;
constexpr int QS_OFF = 0, KS_OFF = 192, VS_OFF = 384, QP_OFF = 576, KP_OFF = 720, VP_OFF = 864;
constexpr float SSC  = 0.14433756729740643f;
constexpr float PSC  = 0.13608276348795434f;
constexpr float PBSC = 0.5773502691896258f;

// ---------------- scratch ----------------
__device__ float g_qkv[NRES * DQKV];
__device__ float g_qp[NRES * 144];
__device__ float g_kp[NRES * 144];
__device__ float g_vp[NRES * 288];
__device__ float g_logits[(size_t)NP * 36];  // [i][c][j] channel-major
__device__ float g_edge[(size_t)NP * 36];    // [i][c][j] softmaxed; c<12 == attn head c
__device__ float g_feats[NRES * DOUT];
__device__ float g_respts[NRES * 288];

__device__ __forceinline__ float gelu_exact(float x) {
    return 0.5f * x * (1.0f + erff(x * 0.70710678118654752f));
}

// ---------------- mma helpers ----------------
__device__ __forceinline__ uint32_t s2u(const void* p) {
    uint32_t a;
    asm("{.reg .u64 t; cvta.to.shared.u64 t, %1; cvt.u32.u64 %0, t;}" : "=r"(a) : "l"(p));
    return a;
}
__device__ __forceinline__ void ldm4(uint32_t r[4], uint32_t a) {
    asm volatile("ldmatrix.sync.aligned.m8n8.x4.shared.b16 {%0,%1,%2,%3},[%4];"
                 : "=r"(r[0]), "=r"(r[1]), "=r"(r[2]), "=r"(r[3]) : "r"(a));
}
__device__ __forceinline__ void ldm4t(uint32_t r[4], uint32_t a) {
    asm volatile("ldmatrix.sync.aligned.m8n8.x4.trans.shared.b16 {%0,%1,%2,%3},[%4];"
                 : "=r"(r[0]), "=r"(r[1]), "=r"(r[2]), "=r"(r[3]) : "r"(a));
}
__device__ __forceinline__ void mma_bf16(float c[4], const uint32_t a[4], uint32_t b0, uint32_t b1) {
    asm volatile(
        "mma.sync.aligned.m16n8k16.row.col.f32.bf16.bf16.f32 "
        "{%0,%1,%2,%3},{%4,%5,%6,%7},{%8,%9},{%0,%1,%2,%3};"
        : "+f"(c[0]), "+f"(c[1]), "+f"(c[2]), "+f"(c[3])
        : "r"(a[0]), "r"(a[1]), "r"(a[2]), "r"(a[3]), "r"(b0), "r"(b1));
}
__device__ __forceinline__ void split1(float v, __nv_bfloat16& h, __nv_bfloat16& l) {
    h = __float2bfloat16_rn(v);
    l = __float2bfloat16_rn(v - __bfloat162float(h));
}
__device__ __forceinline__ void split2(float x, float y, uint32_t& hi, uint32_t& lo) {
    __nv_bfloat16 hx = __float2bfloat16_rn(x), hy = __float2bfloat16_rn(y);
    float rx = x - __bfloat162float(hx), ry = y - __bfloat162float(hy);
    __nv_bfloat162 th = __halves2bfloat162(hx, hy);
    __nv_bfloat162 tl = __floats2bfloat162_rn(rx, ry);
    hi = *reinterpret_cast<uint32_t*>(&th);
    lo = *reinterpret_cast<uint32_t*>(&tl);
}

// ---------------- generic 3-pass bf16 tensor-core GEMM ----------------
// C[M,N] = A[M,K] @ B[K,N] (+bias).  M,N multiples of 128; K multiple of 16.
constexpr int GAP = 24;    // A smem pitch (bf16 elems)
constexpr int GBP = 136;   // B smem pitch
__global__ __launch_bounds__(256) void gemm_mma3(
    const float* __restrict__ A, const float* __restrict__ B, float* __restrict__ C,
    int M, int N, int K, const float* __restrict__ bias)
{
    __shared__ __nv_bfloat16 Ah[128 * GAP], Al[128 * GAP];
    __shared__ __nv_bfloat16 Bh[16 * GBP],  Bl[16 * GBP];
    uint32_t sb_ah = s2u(Ah), sb_al = s2u(Al), sb_bh = s2u(Bh), sb_bl = s2u(Bl);
    int tid = threadIdx.x, lane = tid & 31, w = tid >> 5;
    int bm = blockIdx.y * 128, bn = blockIdx.x * 128;
    int r0 = w * 16;
    uint32_t aAoff = r0 * (GAP * 2) + (lane & 15) * (GAP * 2) + (lane >> 4) * 16;
    int brow = (lane & 7) + ((lane >> 3) & 1) * 8, bc8 = (lane >> 4) * 8;
    uint32_t aBoff = brow * (GBP * 2) + bc8 * 2;

    float acc[16][4] = {};
    for (int k0 = 0; k0 < K; k0 += 16) {
        // stage A 128x16 and B 16x128 (512 float4 each)
#pragma unroll
        for (int rep = 0; rep < 2; rep++) {
            int idx = tid + rep * 256;
            int row = idx >> 2, c4 = (idx & 3) * 4;
            float4 v = *(const float4*)&A[(size_t)(bm + row) * K + k0 + c4];
            split1(v.x, Ah[row * GAP + c4],     Al[row * GAP + c4]);
            split1(v.y, Ah[row * GAP + c4 + 1], Al[row * GAP + c4 + 1]);
            split1(v.z, Ah[row * GAP + c4 + 2], Al[row * GAP + c4 + 2]);
            split1(v.w, Ah[row * GAP + c4 + 3], Al[row * GAP + c4 + 3]);
            int browi = idx >> 5, bc4 = (idx & 31) * 4;
            float4 u = *(const float4*)&B[(size_t)(k0 + browi) * N + bn + bc4];
            split1(u.x, Bh[browi * GBP + bc4],     Bl[browi * GBP + bc4]);
            split1(u.y, Bh[browi * GBP + bc4 + 1], Bl[browi * GBP + bc4 + 1]);
            split1(u.z, Bh[browi * GBP + bc4 + 2], Bl[browi * GBP + bc4 + 2]);
            split1(u.w, Bh[browi * GBP + bc4 + 3], Bl[browi * GBP + bc4 + 3]);
        }
        __syncthreads();
        uint32_t ah[4], al[4];
        ldm4(ah, sb_ah + aAoff);
        ldm4(al, sb_al + aAoff);
#pragma unroll
        for (int n = 0; n < 8; n++) {
            uint32_t bh[4], bl[4];
            ldm4t(bh, sb_bh + aBoff + n * 32);
            ldm4t(bl, sb_bl + aBoff + n * 32);
            mma_bf16(acc[2 * n], ah, bh[0], bh[1]);
            mma_bf16(acc[2 * n], ah, bl[0], bl[1]);
            mma_bf16(acc[2 * n], al, bh[0], bh[1]);
            mma_bf16(acc[2 * n + 1], ah, bh[2], bh[3]);
            mma_bf16(acc[2 * n + 1], ah, bl[2], bl[3]);
            mma_bf16(acc[2 * n + 1], al, bh[2], bh[3]);
        }
        __syncthreads();
    }
    int rlo = bm + r0 + (lane >> 2);
#pragma unroll
    for (int n = 0; n < 16; n++) {
        int c = bn + n * 8 + (lane & 3) * 2;
        float b0 = bias ? bias[c] : 0.f, b1v = bias ? bias[c + 1] : 0.f;
        *(float2*)&C[(size_t)rlo * N + c] = make_float2(acc[n][0] + b0, acc[n][1] + b1v);
        *(float2*)&C[(size_t)(rlo + 8) * N + c] = make_float2(acc[n][2] + b0, acc[n][3] + b1v);
    }
}

// ---------------- points to global frame ----------------
__global__ void k_points(const float* __restrict__ rot, const float* __restrict__ trans) {
    int i = blockIdx.x;
    int t = threadIdx.x;
    const float* q = g_qkv + (size_t)i * DQKV;
    float p0, p1, p2;
    float* dst;
    if (t < 48) {
        int c0 = QP_OFF + t * 3;
        p0 = q[c0]; p1 = q[c0 + 1]; p2 = q[c0 + 2];
        dst = g_qp + i * 144 + t * 3;
    } else if (t < 96) {
        int u = t - 48, c0 = KP_OFF + u * 3;
        p0 = q[c0]; p1 = q[c0 + 1]; p2 = q[c0 + 2];
        dst = g_kp + i * 144 + u * 3;
    } else {
        int u = t - 96, c0 = VP_OFF + u * 3;
        p0 = q[c0]; p1 = q[c0 + 1]; p2 = q[c0 + 2];
        dst = g_vp + i * 288 + u * 3;
    }
    const float* R = rot + i * 9;
    const float* tr = trans + i * 3;
#pragma unroll
    for (int x = 0; x < 3; x++)
        dst[x] = R[x * 3 + 0] * p0 + R[x * 3 + 1] * p1 + R[x * 3 + 2] * p2 + tr[x];
}

// ---------------- pair bias GEMM ----------------
__global__ __launch_bounds__(256) void k_pairbias(
    const float* __restrict__ pair, const float* __restrict__ Wpb)
{
    int i = blockIdx.x / 3;
    int j0 = (blockIdx.x % 3) * 256;
    __shared__ float sP[256][33];
    __shared__ float sW[32][12];
    int tid = threadIdx.x;
    float acc[12] = {};
    const float* prow = pair + ((size_t)i * NRES + j0) * 128;
    for (int k0 = 0; k0 < 128; k0 += 32) {
        for (int idx = tid; idx < 256 * 32; idx += 256) {
            int r = idx >> 5, c = idx & 31;
            sP[r][c] = prow[(size_t)r * 128 + k0 + c];
        }
        for (int idx = tid; idx < 32 * 12; idx += 256)
            sW[idx / 12][idx % 12] = Wpb[(k0 + idx / 12) * 12 + idx % 12];
        __syncthreads();
#pragma unroll 8
        for (int k = 0; k < 32; k++) {
            float a = sP[tid][k];
#pragma unroll
            for (int h = 0; h < 12; h++) acc[h] += a * sW[k][h];
        }
        __syncthreads();
    }
    size_t base = ((size_t)i * 36) * NRES + j0 + tid;
#pragma unroll
    for (int h = 0; h < 12; h++) g_logits[base + (size_t)h * NRES] = acc[h];
}

// ---------------- QK logits per head ----------------
__global__ __launch_bounds__(256) void k_qk(const float* __restrict__ pw) {
    int h = blockIdx.z;
    int i0 = blockIdx.y * 64, j0 = blockIdx.x * 64;
    __shared__ float sq[64][17], sk[64][17], sqp[64][13], skp[64][13];
    int tid = threadIdx.x;
    for (int idx = tid; idx < 1024; idx += 256) {
        int r = idx >> 4, c = idx & 15;
        sq[r][c] = g_qkv[(size_t)(i0 + r) * DQKV + QS_OFF + h * 16 + c];
        sk[r][c] = g_qkv[(size_t)(j0 + r) * DQKV + KS_OFF + h * 16 + c];
    }
    for (int idx = tid; idx < 768; idx += 256) {
        int r = idx / 12, c = idx - r * 12;
        sqp[r][c] = g_qp[(i0 + r) * 144 + h * 12 + c];
        skp[r][c] = g_kp[(j0 + r) * 144 + h * 12 + c];
    }
    float sph = log1pf(__expf(pw[h]));
    __syncthreads();
    int tx = tid & 15, ty = tid >> 4;
    float sl[4][4] = {}, pl[4][4] = {};
#pragma unroll
    for (int k = 0; k < 16; k++) {
        float a[4], b[4];
#pragma unroll
        for (int q = 0; q < 4; q++) a[q] = sq[ty * 4 + q][k];
#pragma unroll
        for (int r = 0; r < 4; r++) b[r] = sk[tx * 4 + r][k];
#pragma unroll
        for (int q = 0; q < 4; q++)
#pragma unroll
            for (int r = 0; r < 4; r++) sl[q][r] += a[q] * b[r];
    }
#pragma unroll
    for (int k = 0; k < 12; k++) {
        float a[4], b[4];
#pragma unroll
        for (int q = 0; q < 4; q++) a[q] = sqp[ty * 4 + q][k];
#pragma unroll
        for (int r = 0; r < 4; r++) b[r] = skp[tx * 4 + r][k];
#pragma unroll
        for (int q = 0; q < 4; q++)
#pragma unroll
            for (int r = 0; r < 4; r++) pl[q][r] += a[q] * b[r];
    }
#pragma unroll
    for (int q = 0; q < 4; q++) {
        int i = i0 + ty * 4 + q;
        size_t bc = ((size_t)i * 36 + h) * NRES;
#pragma unroll
        for (int r = 0; r < 4; r++) {
            int j = j0 + tx * 4 + r;
            float plv = pl[q][r] * sph;
            float pb = g_logits[bc + j];
            g_logits[bc + j] = SSC * sl[q][r] + PSC * plv + PBSC * pb;
            g_logits[bc + (size_t)12 * NRES + j] = plv;
            g_logits[bc + (size_t)24 * NRES + j] = sl[q][r];
        }
    }
}

// ---------------- softmax ----------------
__global__ __launch_bounds__(256) void k_softmax2() {
    int i = blockIdx.x;
    int warp = threadIdx.x >> 5, lane = threadIdx.x & 31;
    for (int c = warp; c < 36; c += 8) {
        const float* src = g_logits + ((size_t)i * 36 + c) * NRES;
        float v[24];
        float m = -1e30f;
#pragma unroll
        for (int t = 0; t < 24; t++) { v[t] = src[lane + t * 32]; m = fmaxf(m, v[t]); }
#pragma unroll
        for (int s = 16; s > 0; s >>= 1) m = fmaxf(m, __shfl_xor_sync(0xffffffffu, m, s));
        float sum = 0.f;
#pragma unroll
        for (int t = 0; t < 24; t++) { v[t] = __expf(v[t] - m); sum += v[t]; }
#pragma unroll
        for (int s = 16; s > 0; s >>= 1) sum += __shfl_xor_sync(0xffffffffu, sum, s);
        float inv = 1.f / sum;
        float* dst = g_edge + ((size_t)i * 36 + c) * NRES;
#pragma unroll
        for (int t = 0; t < 24; t++) dst[lane + t * 32] = v[t] * inv;
    }
}

// ---------------- res_pair ----------------
__global__ __launch_bounds__(128) void k_respair(const float* __restrict__ pair) {
    int i = blockIdx.x;
    __shared__ float att[12][768];
    int tid = threadIdx.x;
    for (int idx = tid; idx < 12 * 768; idx += 128) {
        int h = idx / 768, j = idx - h * 768;
        att[h][j] = g_edge[((size_t)i * 36 + h) * NRES + j];
    }
    __syncthreads();
    int d4 = tid & 31, jp = tid >> 5;
    float acc[12][4] = {};
    for (int j = jp; j < NRES; j += 4) {
        float4 v = *(const float4*)(pair + ((size_t)i * NRES + j) * 128 + d4 * 4);
#pragma unroll
        for (int h = 0; h < 12; h++) {
            float a = att[h][j];
            acc[h][0] += a * v.x; acc[h][1] += a * v.y;
            acc[h][2] += a * v.z; acc[h][3] += a * v.w;
        }
    }
    __syncthreads();
    float* red = &att[0][0];
#pragma unroll
    for (int h = 0; h < 12; h++) {
        float* base = red + ((jp * 12 + h) << 7) + d4 * 4;
        base[0] = acc[h][0]; base[1] = acc[h][1]; base[2] = acc[h][2]; base[3] = acc[h][3];
    }
    __syncthreads();
    for (int idx = tid; idx < 1536; idx += 128) {
        int h = idx >> 7, d = idx & 127;
        float s = red[((0 * 12 + h) << 7) + d] + red[((1 * 12 + h) << 7) + d]
                + red[((2 * 12 + h) << 7) + d] + red[((3 * 12 + h) << 7) + d];
        g_feats[(size_t)i * DOUT + 192 + h * 128 + d] = s;
    }
}

// ---------------- res_scalar + res_pts ----------------
__global__ __launch_bounds__(256) void k_resv() {
    int h = blockIdx.y;
    int i0 = blockIdx.x * 64;
    __shared__ float a[64][65];
    __shared__ float v[64][40];
    int tid = threadIdx.x;
    int io = tid & 63, og = tid >> 6;
    float acc[10] = {};
    for (int j0 = 0; j0 < NRES; j0 += 64) {
        for (int idx = tid; idx < 4096; idx += 256) {
            int ii = idx >> 6, jj = idx & 63;
            a[ii][jj] = g_edge[((size_t)(i0 + ii) * 36 + h) * NRES + j0 + jj];
        }
        for (int idx = tid; idx < 64 * 40; idx += 256) {
            int jj = idx / 40, o = idx - jj * 40;
            float val;
            if (o < 16) val = g_qkv[(size_t)(j0 + jj) * DQKV + VS_OFF + h * 16 + o];
            else        val = g_vp[(size_t)(j0 + jj) * 288 + h * 24 + (o - 16)];
            v[jj][o] = val;
        }
        __syncthreads();
#pragma unroll 4
        for (int jj = 0; jj < 64; jj++) {
            float av = a[io][jj];
#pragma unroll
            for (int q = 0; q < 10; q++) acc[q] += av * v[jj][og * 10 + q];
        }
        __syncthreads();
    }
#pragma unroll
    for (int q = 0; q < 10; q++) {
        int o = og * 10 + q;
        if (o < 16) g_feats[(size_t)(i0 + io) * DOUT + h * 16 + o] = acc[q];
        else        g_respts[(size_t)(i0 + io) * 288 + h * 24 + (o - 16)] = acc[q];
    }
}

// ---------------- inverse rigid + norms ----------------
__global__ void k_local(const float* __restrict__ rot, const float* __restrict__ trans) {
    int i = blockIdx.x;
    int t = threadIdx.x;
    int h = t / 8, k = t - h * 8;
    const float* R = rot + i * 9;
    const float* tr = trans + i * 3;
    float vy[3];
#pragma unroll
    for (int y = 0; y < 3; y++)
        vy[y] = g_respts[(size_t)i * 288 + h * 24 + k * 3 + y] - tr[y];
    float s = 1e-8f;
    float* fbase = g_feats + (size_t)i * DOUT;
#pragma unroll
    for (int x = 0; x < 3; x++) {
        float l = R[0 * 3 + x] * vy[0] + R[1 * 3 + x] * vy[1] + R[2 * 3 + x] * vy[2];
        fbase[1728 + h * 24 + k * 3 + x] = l;
        s += l * l;
    }
    fbase[2016 + h * 8 + k] = sqrtf(s);
}

// ================= pair MLP on tensor cores (bf16 2-split, 3-pass), 512 threads =================
constexpr int W1P = 136, W2P = 136, EP = 56, HP = 136;
constexpr int OFF_W1H = 0;
constexpr int OFF_W1L = OFF_W1H + 48 * W1P * 2;
constexpr int OFF_W2H = OFF_W1L + 48 * W1P * 2;
constexpr int OFF_W2L = OFF_W2H + 128 * W2P * 2;
constexpr int OFF_EH  = OFF_W2L + 128 * W2P * 2;
constexpr int OFF_EL  = OFF_EH + 128 * EP * 2;
constexpr int OFF_HH  = OFF_EL + 128 * EP * 2;
constexpr int OFF_HL  = OFF_HH + 128 * HP * 2;
constexpr int OFF_B1  = OFF_HL + 128 * HP * 2;
constexpr int OFF_B2  = OFF_B1 + 512;
constexpr int MLP_SMEM = OFF_B2 + 512;   // 195072 bytes

__global__ __launch_bounds__(512, 1) void k_pairmlp_mma(
    const float* __restrict__ Wp1, const float* __restrict__ bp1,
    const float* __restrict__ Wp2, const float* __restrict__ bp2,
    float* __restrict__ out)
{
    extern __shared__ char sm[];
    uint32_t sb = s2u(sm);
    int tid = threadIdx.x, lane = tid & 31, w = tid >> 5;

    for (int idx = tid; idx < 48 * 128; idx += 512) {
        int k = idx >> 7, n = idx & 127;
        float v = (k < 36) ? Wp1[k * 128 + n] : 0.f;
        __nv_bfloat16 h = __float2bfloat16_rn(v);
        ((__nv_bfloat16*)(sm + OFF_W1H))[k * W1P + n] = h;
        ((__nv_bfloat16*)(sm + OFF_W1L))[k * W1P + n] = __float2bfloat16_rn(v - __bfloat162float(h));
    }
    for (int idx = tid; idx < 128 * 128; idx += 512) {
        int k = idx >> 7, n = idx & 127;
        float v = Wp2[idx];
        __nv_bfloat16 h = __float2bfloat16_rn(v);
        ((__nv_bfloat16*)(sm + OFF_W2H))[k * W2P + n] = h;
        ((__nv_bfloat16*)(sm + OFF_W2L))[k * W2P + n] = __float2bfloat16_rn(v - __bfloat162float(h));
    }
    if (tid < 128) {
        ((float*)(sm + OFF_B1))[tid] = bp1[tid];
        ((float*)(sm + OFF_B2))[tid] = bp2[tid];
    }
    for (int idx = tid; idx < 128 * 12; idx += 512) {
        int r = idx / 12, c = 36 + idx % 12;
        ((__nv_bfloat16*)(sm + OFF_EH))[r * EP + c] = __float2bfloat16_rn(0.f);
        ((__nv_bfloat16*)(sm + OFF_EL))[r * EP + c] = __float2bfloat16_rn(0.f);
    }

    // warp tiling: 16 warps = 8 row-groups x 2 col-groups
    int r0 = (w >> 1) * 16;
    int cb = (w & 1) * 64;
    uint32_t aAoffE = r0 * (EP * 2) + (lane & 15) * (EP * 2) + (lane >> 4) * 16;
    uint32_t aAoffH = r0 * (HP * 2) + (lane & 15) * (HP * 2) + (lane >> 4) * 16;
    int brow = (lane & 7) + ((lane >> 3) & 1) * 8, bc8 = (lane >> 4) * 8;
    uint32_t aBoff1 = brow * (W1P * 2) + (bc8 + cb) * 2;
    uint32_t aBoff2 = brow * (W2P * 2) + (bc8 + cb) * 2;

    const float* b1 = (const float*)(sm + OFF_B1);
    const float* b2 = (const float*)(sm + OFF_B2);

    for (int t = blockIdx.x; t < 4608; t += gridDim.x) {
        __syncthreads();
        {
            int i = t / 6, j0 = (t % 6) * 128;
            const float* src = g_edge + ((size_t)i * 36) * NRES + j0;
            for (int idx = tid; idx < 36 * 128; idx += 512) {
                int c = idx >> 7, jj = idx & 127;
                float v = src[(size_t)c * NRES + jj];
                __nv_bfloat16 h = __float2bfloat16_rn(v);
                ((__nv_bfloat16*)(sm + OFF_EH))[jj * EP + c] = h;
                ((__nv_bfloat16*)(sm + OFF_EL))[jj * EP + c] =
                    __float2bfloat16_rn(v - __bfloat162float(h));
            }
        }
        __syncthreads();

        // ---- layer 1 ----
        float acc[8][4];
#pragma unroll
        for (int n = 0; n < 8; n++) {
            float2 bb = *(const float2*)&b1[cb + n * 8 + (lane & 3) * 2];
            acc[n][0] = bb.x; acc[n][1] = bb.y; acc[n][2] = bb.x; acc[n][3] = bb.y;
        }
#pragma unroll
        for (int ks = 0; ks < 3; ks++) {
            uint32_t ah[4], al[4];
            ldm4(ah, sb + OFF_EH + aAoffE + ks * 32);
            ldm4(al, sb + OFF_EL + aAoffE + ks * 32);
#pragma unroll
            for (int n = 0; n < 4; n++) {
                uint32_t bh[4], bl[4];
                ldm4t(bh, sb + OFF_W1H + ks * 16 * (W1P * 2) + aBoff1 + n * 32);
                ldm4t(bl, sb + OFF_W1L + ks * 16 * (W1P * 2) + aBoff1 + n * 32);
                mma_bf16(acc[2 * n], ah, bh[0], bh[1]);
                mma_bf16(acc[2 * n], ah, bl[0], bl[1]);
                mma_bf16(acc[2 * n], al, bh[0], bh[1]);
                mma_bf16(acc[2 * n + 1], ah, bh[2], bh[3]);
                mma_bf16(acc[2 * n + 1], ah, bl[2], bl[3]);
                mma_bf16(acc[2 * n + 1], al, bh[2], bh[3]);
            }
        }
        {
            int rlo = r0 + (lane >> 2);
#pragma unroll
            for (int n = 0; n < 8; n++) {
                int c = cb + n * 8 + (lane & 3) * 2;
                float g0 = gelu_exact(acc[n][0]), g1 = gelu_exact(acc[n][1]);
                float g2 = gelu_exact(acc[n][2]), g3 = gelu_exact(acc[n][3]);
                uint32_t h01, l01, h23, l23;
                split2(g0, g1, h01, l01);
                split2(g2, g3, h23, l23);
                *(uint32_t*)(sm + OFF_HH + rlo * (HP * 2) + c * 2) = h01;
                *(uint32_t*)(sm + OFF_HL + rlo * (HP * 2) + c * 2) = l01;
                *(uint32_t*)(sm + OFF_HH + (rlo + 8) * (HP * 2) + c * 2) = h23;
                *(uint32_t*)(sm + OFF_HL + (rlo + 8) * (HP * 2) + c * 2) = l23;
            }
        }
        __syncthreads();

        // ---- layer 2 ----
#pragma unroll
        for (int n = 0; n < 8; n++) {
            float2 bb = *(const float2*)&b2[cb + n * 8 + (lane & 3) * 2];
            acc[n][0] = bb.x; acc[n][1] = bb.y; acc[n][2] = bb.x; acc[n][3] = bb.y;
        }
#pragma unroll
        for (int ks = 0; ks < 8; ks++) {
            uint32_t ah[4], al[4];
            ldm4(ah, sb + OFF_HH + aAoffH + ks * 32);
            ldm4(al, sb + OFF_HL + aAoffH + ks * 32);
#pragma unroll
            for (int n = 0; n < 4; n++) {
                uint32_t bh[4], bl[4];
                ldm4t(bh, sb + OFF_W2H + ks * 16 * (W2P * 2) + aBoff2 + n * 32);
                ldm4t(bl, sb + OFF_W2L + ks * 16 * (W2P * 2) + aBoff2 + n * 32);
                mma_bf16(acc[2 * n], ah, bh[0], bh[1]);
                mma_bf16(acc[2 * n], ah, bl[0], bl[1]);
                mma_bf16(acc[2 * n], al, bh[0], bh[1]);
                mma_bf16(acc[2 * n + 1], ah, bh[2], bh[3]);
                mma_bf16(acc[2 * n + 1], ah, bl[2], bl[3]);
                mma_bf16(acc[2 * n + 1], al, bh[2], bh[3]);
            }
        }
        {
            float* dst = out + (size_t)t * 128 * 128;
            int rlo = r0 + (lane >> 2);
#pragma unroll
            for (int n = 0; n < 8; n++) {
                int c = cb + n * 8 + (lane & 3) * 2;
                *(float2*)&dst[(size_t)rlo * 128 + c] = make_float2(acc[n][0], acc[n][1]);
                *(float2*)&dst[(size_t)(rlo + 8) * 128 + c] = make_float2(acc[n][2], acc[n][3]);
            }
        }
    }
}

// ---------------- host launcher ----------------
extern "C" void kernel_launch(void* const* d_in, const int* in_sizes, int n_in,
                              void* d_out, int out_size) {
    const float* scalar = (const float*)d_in[0];
    const float* pair   = (const float*)d_in[1];
    const float* rot    = (const float*)d_in[2];
    const float* trans  = (const float*)d_in[3];
    // d_in[4] = mask (all true; no-op)
    const float* Wqkv = (const float*)d_in[5];
    const float* Wpb  = (const float*)d_in[6];
    const float* pw   = (const float*)d_in[7];
    const float* Wout = (const float*)d_in[8];
    const float* bout = (const float*)d_in[9];
    const float* Wp1  = (const float*)d_in[10];
    const float* bp1  = (const float*)d_in[11];
    const float* Wp2  = (const float*)d_in[12];
    const float* bp2  = (const float*)d_in[13];
    float* out = (float*)d_out;

    cudaFuncSetAttribute(k_pairmlp_mma, cudaFuncAttributeMaxDynamicSharedMemorySize, MLP_SMEM);

    float* g_qkv_p;   cudaGetSymbolAddress((void**)&g_qkv_p, g_qkv);
    float* g_feats_p; cudaGetSymbolAddress((void**)&g_feats_p, g_feats);

    // 1) qkv projection (tensor cores, 3-pass)
    gemm_mma3<<<dim3(DQKV / 128, NRES / 128), 256>>>(scalar, Wqkv, g_qkv_p, NRES, DQKV, DSC, nullptr);
    // 2) points to global frame
    k_points<<<NRES, 192>>>(rot, trans);
    // 3) pair bias GEMM
    k_pairbias<<<NRES * 3, 256>>>(pair, Wpb);
    // 4) QK logits + combine
    k_qk<<<dim3(NRES / 64, NRES / 64, NH), 256>>>(pw);
    // 5) softmax
    k_softmax2<<<NRES, 256>>>();
    // 6) res_pair
    k_respair<<<NRES, 128>>>(pair);
    // 7) res_scalar + res_pts
    k_resv<<<dim3(NRES / 64, NH), 256>>>();
    // 8) local frame + norms
    k_local<<<NRES, 96>>>(rot, trans);
    // 9) scalar_out (tensor cores, 3-pass)
    gemm_mma3<<<dim3(DSC / 128, NRES / 128), 256>>>(g_feats_p, Wout, out, NRES, DSC, DOUT, bout);
    // 10) pair MLP (tensor cores, 512 threads)
    k_pairmlp_mma<<<152, 512, MLP_SMEM>>>(Wp1, bp1, Wp2, bp2, out + NRES * DSC);
}

// round 4
// speedup vs baseline: 2.3541x; 1.0098x over previous
#include <cuda_runtime.h>
#include <cuda_bf16.h>
#include <math.h>
#include <stdint.h>

// ---------------- problem constants ----------------
constexpr int NRES  = 768;
constexpr int NH    = 12;
constexpr long long NP = (long long)NRES * NRES;   // 589824
constexpr int DQKV  = 1152;
constexpr int DSC   = 384;
constexpr int DOUT  = 2112;
constexpr int QS_OFF = 0, KS_OFF = 192, VS_OFF = 384, QP_OFF = 576, KP_OFF = 720, VP_OFF = 864;
constexpr float SSC  = 0.14433756729740643f;
constexpr float PSC  = 0.13608276348795434f;
constexpr float PBSC = 0.5773502691896258f;

// ---------------- scratch ----------------
__device__ float g_qkv[NRES * DQKV];
__device__ float g_qp[NRES * 144];
__device__ float g_kp[NRES * 144];
__device__ float g_vp[NRES * 288];
__device__ float g_logits[(size_t)NP * 36];  // [i][c][j] channel-major
__device__ float g_edge[(size_t)NP * 36];    // [i][c][j] softmaxed; c<12 == attn head c
__device__ float g_feats[NRES * DOUT];
__device__ float g_respts[NRES * 288];

__device__ __forceinline__ float gelu_exact(float x) {
    return 0.5f * x * (1.0f + erff(x * 0.70710678118654752f));
}

// ---------------- mma helpers ----------------
__device__ __forceinline__ uint32_t s2u(const void* p) {
    uint32_t a;
    asm("{.reg .u64 t; cvta.to.shared.u64 t, %1; cvt.u32.u64 %0, t;}" : "=r"(a) : "l"(p));
    return a;
}
__device__ __forceinline__ void ldm4(uint32_t r[4], uint32_t a) {
    asm volatile("ldmatrix.sync.aligned.m8n8.x4.shared.b16 {%0,%1,%2,%3},[%4];"
                 : "=r"(r[0]), "=r"(r[1]), "=r"(r[2]), "=r"(r[3]) : "r"(a));
}
__device__ __forceinline__ void ldm4t(uint32_t r[4], uint32_t a) {
    asm volatile("ldmatrix.sync.aligned.m8n8.x4.trans.shared.b16 {%0,%1,%2,%3},[%4];"
                 : "=r"(r[0]), "=r"(r[1]), "=r"(r[2]), "=r"(r[3]) : "r"(a));
}
__device__ __forceinline__ void mma_bf16(float c[4], const uint32_t a[4], uint32_t b0, uint32_t b1) {
    asm volatile(
        "mma.sync.aligned.m16n8k16.row.col.f32.bf16.bf16.f32 "
        "{%0,%1,%2,%3},{%4,%5,%6,%7},{%8,%9},{%0,%1,%2,%3};"
        : "+f"(c[0]), "+f"(c[1]), "+f"(c[2]), "+f"(c[3])
        : "r"(a[0]), "r"(a[1]), "r"(a[2]), "r"(a[3]), "r"(b0), "r"(b1));
}
__device__ __forceinline__ void split1(float v, __nv_bfloat16& h, __nv_bfloat16& l) {
    h = __float2bfloat16_rn(v);
    l = __float2bfloat16_rn(v - __bfloat162float(h));
}
__device__ __forceinline__ void split2(float x, float y, uint32_t& hi, uint32_t& lo) {
    __nv_bfloat16 hx = __float2bfloat16_rn(x), hy = __float2bfloat16_rn(y);
    float rx = x - __bfloat162float(hx), ry = y - __bfloat162float(hy);
    __nv_bfloat162 th = __halves2bfloat162(hx, hy);
    __nv_bfloat162 tl = __floats2bfloat162_rn(rx, ry);
    hi = *reinterpret_cast<uint32_t*>(&th);
    lo = *reinterpret_cast<uint32_t*>(&tl);
}

// ---------------- generic 3-pass bf16 tensor-core GEMM ----------------
constexpr int GAP = 24;
constexpr int GBP = 136;
__global__ __launch_bounds__(256) void gemm_mma3(
    const float* __restrict__ A, const float* __restrict__ B, float* __restrict__ C,
    int M, int N, int K, const float* __restrict__ bias)
{
    __shared__ __nv_bfloat16 Ah[128 * GAP], Al[128 * GAP];
    __shared__ __nv_bfloat16 Bh[16 * GBP],  Bl[16 * GBP];
    uint32_t sb_ah = s2u(Ah), sb_al = s2u(Al), sb_bh = s2u(Bh), sb_bl = s2u(Bl);
    int tid = threadIdx.x, lane = tid & 31, w = tid >> 5;
    int bm = blockIdx.y * 128, bn = blockIdx.x * 128;
    int r0 = w * 16;
    uint32_t aAoff = r0 * (GAP * 2) + (lane & 15) * (GAP * 2) + (lane >> 4) * 16;
    int brow = (lane & 7) + ((lane >> 3) & 1) * 8, bc8 = (lane >> 4) * 8;
    uint32_t aBoff = brow * (GBP * 2) + bc8 * 2;

    float acc[16][4] = {};
    for (int k0 = 0; k0 < K; k0 += 16) {
#pragma unroll
        for (int rep = 0; rep < 2; rep++) {
            int idx = tid + rep * 256;
            int row = idx >> 2, c4 = (idx & 3) * 4;
            float4 v = *(const float4*)&A[(size_t)(bm + row) * K + k0 + c4];
            split1(v.x, Ah[row * GAP + c4],     Al[row * GAP + c4]);
            split1(v.y, Ah[row * GAP + c4 + 1], Al[row * GAP + c4 + 1]);
            split1(v.z, Ah[row * GAP + c4 + 2], Al[row * GAP + c4 + 2]);
            split1(v.w, Ah[row * GAP + c4 + 3], Al[row * GAP + c4 + 3]);
            int browi = idx >> 5, bc4 = (idx & 31) * 4;
            float4 u = *(const float4*)&B[(size_t)(k0 + browi) * N + bn + bc4];
            split1(u.x, Bh[browi * GBP + bc4],     Bl[browi * GBP + bc4]);
            split1(u.y, Bh[browi * GBP + bc4 + 1], Bl[browi * GBP + bc4 + 1]);
            split1(u.z, Bh[browi * GBP + bc4 + 2], Bl[browi * GBP + bc4 + 2]);
            split1(u.w, Bh[browi * GBP + bc4 + 3], Bl[browi * GBP + bc4 + 3]);
        }
        __syncthreads();
        uint32_t ah[4], al[4];
        ldm4(ah, sb_ah + aAoff);
        ldm4(al, sb_al + aAoff);
#pragma unroll
        for (int n = 0; n < 8; n++) {
            uint32_t bh[4], bl[4];
            ldm4t(bh, sb_bh + aBoff + n * 32);
            ldm4t(bl, sb_bl + aBoff + n * 32);
            mma_bf16(acc[2 * n], ah, bh[0], bh[1]);
            mma_bf16(acc[2 * n], ah, bl[0], bl[1]);
            mma_bf16(acc[2 * n], al, bh[0], bh[1]);
            mma_bf16(acc[2 * n + 1], ah, bh[2], bh[3]);
            mma_bf16(acc[2 * n + 1], ah, bl[2], bl[3]);
            mma_bf16(acc[2 * n + 1], al, bh[2], bh[3]);
        }
        __syncthreads();
    }
    int rlo = bm + r0 + (lane >> 2);
#pragma unroll
    for (int n = 0; n < 16; n++) {
        int c = bn + n * 8 + (lane & 3) * 2;
        float b0 = bias ? bias[c] : 0.f, b1v = bias ? bias[c + 1] : 0.f;
        *(float2*)&C[(size_t)rlo * N + c] = make_float2(acc[n][0] + b0, acc[n][1] + b1v);
        *(float2*)&C[(size_t)(rlo + 8) * N + c] = make_float2(acc[n][2] + b0, acc[n][3] + b1v);
    }
}

// ---------------- points to global frame ----------------
__global__ void k_points(const float* __restrict__ rot, const float* __restrict__ trans) {
    int i = blockIdx.x;
    int t = threadIdx.x;
    const float* q = g_qkv + (size_t)i * DQKV;
    float p0, p1, p2;
    float* dst;
    if (t < 48) {
        int c0 = QP_OFF + t * 3;
        p0 = q[c0]; p1 = q[c0 + 1]; p2 = q[c0 + 2];
        dst = g_qp + i * 144 + t * 3;
    } else if (t < 96) {
        int u = t - 48, c0 = KP_OFF + u * 3;
        p0 = q[c0]; p1 = q[c0 + 1]; p2 = q[c0 + 2];
        dst = g_kp + i * 144 + u * 3;
    } else {
        int u = t - 96, c0 = VP_OFF + u * 3;
        p0 = q[c0]; p1 = q[c0 + 1]; p2 = q[c0 + 2];
        dst = g_vp + i * 288 + u * 3;
    }
    const float* R = rot + i * 9;
    const float* tr = trans + i * 3;
#pragma unroll
    for (int x = 0; x < 3; x++)
        dst[x] = R[x * 3 + 0] * p0 + R[x * 3 + 1] * p1 + R[x * 3 + 2] * p2 + tr[x];
}

// ---------------- pair bias GEMM ----------------
__global__ __launch_bounds__(256) void k_pairbias(
    const float* __restrict__ pair, const float* __restrict__ Wpb)
{
    int i = blockIdx.x / 3;
    int j0 = (blockIdx.x % 3) * 256;
    __shared__ float sP[256][33];
    __shared__ float sW[32][12];
    int tid = threadIdx.x;
    float acc[12] = {};
    const float* prow = pair + ((size_t)i * NRES + j0) * 128;
    for (int k0 = 0; k0 < 128; k0 += 32) {
        for (int idx = tid; idx < 256 * 32; idx += 256) {
            int r = idx >> 5, c = idx & 31;
            sP[r][c] = prow[(size_t)r * 128 + k0 + c];
        }
        for (int idx = tid; idx < 32 * 12; idx += 256)
            sW[idx / 12][idx % 12] = Wpb[(k0 + idx / 12) * 12 + idx % 12];
        __syncthreads();
#pragma unroll 8
        for (int k = 0; k < 32; k++) {
            float a = sP[tid][k];
#pragma unroll
            for (int h = 0; h < 12; h++) acc[h] += a * sW[k][h];
        }
        __syncthreads();
    }
    size_t base = ((size_t)i * 36) * NRES + j0 + tid;
#pragma unroll
    for (int h = 0; h < 12; h++) g_logits[base + (size_t)h * NRES] = acc[h];
}

// ---------------- QK logits per head ----------------
__global__ __launch_bounds__(256) void k_qk(const float* __restrict__ pw) {
    int h = blockIdx.z;
    int i0 = blockIdx.y * 64, j0 = blockIdx.x * 64;
    __shared__ float sq[64][17], sk[64][17], sqp[64][13], skp[64][13];
    int tid = threadIdx.x;
    for (int idx = tid; idx < 1024; idx += 256) {
        int r = idx >> 4, c = idx & 15;
        sq[r][c] = g_qkv[(size_t)(i0 + r) * DQKV + QS_OFF + h * 16 + c];
        sk[r][c] = g_qkv[(size_t)(j0 + r) * DQKV + KS_OFF + h * 16 + c];
    }
    for (int idx = tid; idx < 768; idx += 256) {
        int r = idx / 12, c = idx - r * 12;
        sqp[r][c] = g_qp[(i0 + r) * 144 + h * 12 + c];
        skp[r][c] = g_kp[(j0 + r) * 144 + h * 12 + c];
    }
    float sph = log1pf(__expf(pw[h]));
    __syncthreads();
    int tx = tid & 15, ty = tid >> 4;
    float sl[4][4] = {}, pl[4][4] = {};
#pragma unroll
    for (int k = 0; k < 16; k++) {
        float a[4], b[4];
#pragma unroll
        for (int q = 0; q < 4; q++) a[q] = sq[ty * 4 + q][k];
#pragma unroll
        for (int r = 0; r < 4; r++) b[r] = sk[tx * 4 + r][k];
#pragma unroll
        for (int q = 0; q < 4; q++)
#pragma unroll
            for (int r = 0; r < 4; r++) sl[q][r] += a[q] * b[r];
    }
#pragma unroll
    for (int k = 0; k < 12; k++) {
        float a[4], b[4];
#pragma unroll
        for (int q = 0; q < 4; q++) a[q] = sqp[ty * 4 + q][k];
#pragma unroll
        for (int r = 0; r < 4; r++) b[r] = skp[tx * 4 + r][k];
#pragma unroll
        for (int q = 0; q < 4; q++)
#pragma unroll
            for (int r = 0; r < 4; r++) pl[q][r] += a[q] * b[r];
    }
#pragma unroll
    for (int q = 0; q < 4; q++) {
        int i = i0 + ty * 4 + q;
        size_t bc = ((size_t)i * 36 + h) * NRES;
#pragma unroll
        for (int r = 0; r < 4; r++) {
            int j = j0 + tx * 4 + r;
            float plv = pl[q][r] * sph;
            float pb = g_logits[bc + j];
            g_logits[bc + j] = SSC * sl[q][r] + PSC * plv + PBSC * pb;
            g_logits[bc + (size_t)12 * NRES + j] = plv;
            g_logits[bc + (size_t)24 * NRES + j] = sl[q][r];
        }
    }
}

// ---------------- softmax ----------------
__global__ __launch_bounds__(256) void k_softmax2() {
    int i = blockIdx.x;
    int warp = threadIdx.x >> 5, lane = threadIdx.x & 31;
    for (int c = warp; c < 36; c += 8) {
        const float* src = g_logits + ((size_t)i * 36 + c) * NRES;
        float v[24];
        float m = -1e30f;
#pragma unroll
        for (int t = 0; t < 24; t++) { v[t] = src[lane + t * 32]; m = fmaxf(m, v[t]); }
#pragma unroll
        for (int s = 16; s > 0; s >>= 1) m = fmaxf(m, __shfl_xor_sync(0xffffffffu, m, s));
        float sum = 0.f;
#pragma unroll
        for (int t = 0; t < 24; t++) { v[t] = __expf(v[t] - m); sum += v[t]; }
#pragma unroll
        for (int s = 16; s > 0; s >>= 1) sum += __shfl_xor_sync(0xffffffffu, sum, s);
        float inv = 1.f / sum;
        float* dst = g_edge + ((size_t)i * 36 + c) * NRES;
#pragma unroll
        for (int t = 0; t < 24; t++) dst[lane + t * 32] = v[t] * inv;
    }
}

// ---------------- res_pair ----------------
__global__ __launch_bounds__(128) void k_respair(const float* __restrict__ pair) {
    int i = blockIdx.x;
    __shared__ float att[12][768];
    int tid = threadIdx.x;
    for (int idx = tid; idx < 12 * 768; idx += 128) {
        int h = idx / 768, j = idx - h * 768;
        att[h][j] = g_edge[((size_t)i * 36 + h) * NRES + j];
    }
    __syncthreads();
    int d4 = tid & 31, jp = tid >> 5;
    float acc[12][4] = {};
    for (int j = jp; j < NRES; j += 4) {
        float4 v = *(const float4*)(pair + ((size_t)i * NRES + j) * 128 + d4 * 4);
#pragma unroll
        for (int h = 0; h < 12; h++) {
            float a = att[h][j];
            acc[h][0] += a * v.x; acc[h][1] += a * v.y;
            acc[h][2] += a * v.z; acc[h][3] += a * v.w;
        }
    }
    __syncthreads();
    float* red = &att[0][0];
#pragma unroll
    for (int h = 0; h < 12; h++) {
        float* base = red + ((jp * 12 + h) << 7) + d4 * 4;
        base[0] = acc[h][0]; base[1] = acc[h][1]; base[2] = acc[h][2]; base[3] = acc[h][3];
    }
    __syncthreads();
    for (int idx = tid; idx < 1536; idx += 128) {
        int h = idx >> 7, d = idx & 127;
        float s = red[((0 * 12 + h) << 7) + d] + red[((1 * 12 + h) << 7) + d]
                + red[((2 * 12 + h) << 7) + d] + red[((3 * 12 + h) << 7) + d];
        g_feats[(size_t)i * DOUT + 192 + h * 128 + d] = s;
    }
}

// ---------------- res_scalar + res_pts ----------------
__global__ __launch_bounds__(256) void k_resv() {
    int h = blockIdx.y;
    int i0 = blockIdx.x * 64;
    __shared__ float a[64][65];
    __shared__ float v[64][40];
    int tid = threadIdx.x;
    int io = tid & 63, og = tid >> 6;
    float acc[10] = {};
    for (int j0 = 0; j0 < NRES; j0 += 64) {
        for (int idx = tid; idx < 4096; idx += 256) {
            int ii = idx >> 6, jj = idx & 63;
            a[ii][jj] = g_edge[((size_t)(i0 + ii) * 36 + h) * NRES + j0 + jj];
        }
        for (int idx = tid; idx < 64 * 40; idx += 256) {
            int jj = idx / 40, o = idx - jj * 40;
            float val;
            if (o < 16) val = g_qkv[(size_t)(j0 + jj) * DQKV + VS_OFF + h * 16 + o];
            else        val = g_vp[(size_t)(j0 + jj) * 288 + h * 24 + (o - 16)];
            v[jj][o] = val;
        }
        __syncthreads();
#pragma unroll 4
        for (int jj = 0; jj < 64; jj++) {
            float av = a[io][jj];
#pragma unroll
            for (int q = 0; q < 10; q++) acc[q] += av * v[jj][og * 10 + q];
        }
        __syncthreads();
    }
#pragma unroll
    for (int q = 0; q < 10; q++) {
        int o = og * 10 + q;
        if (o < 16) g_feats[(size_t)(i0 + io) * DOUT + h * 16 + o] = acc[q];
        else        g_respts[(size_t)(i0 + io) * 288 + h * 24 + (o - 16)] = acc[q];
    }
}

// ---------------- inverse rigid + norms ----------------
__global__ void k_local(const float* __restrict__ rot, const float* __restrict__ trans) {
    int i = blockIdx.x;
    int t = threadIdx.x;
    int h = t / 8, k = t - h * 8;
    const float* R = rot + i * 9;
    const float* tr = trans + i * 3;
    float vy[3];
#pragma unroll
    for (int y = 0; y < 3; y++)
        vy[y] = g_respts[(size_t)i * 288 + h * 24 + k * 3 + y] - tr[y];
    float s = 1e-8f;
    float* fbase = g_feats + (size_t)i * DOUT;
#pragma unroll
    for (int x = 0; x < 3; x++) {
        float l = R[0 * 3 + x] * vy[0] + R[1 * 3 + x] * vy[1] + R[2 * 3 + x] * vy[2];
        fbase[1728 + h * 24 + k * 3 + x] = l;
        s += l * l;
    }
    fbase[2016 + h * 8 + k] = sqrtf(s);
}

// ================= pair MLP: register-chained, per-warp m16 x n128 =================
// layer1 acc fragments ARE layer2 A fragments -> H never touches smem; no block syncs in loop.
constexpr int W1P = 136, W2P = 136, EP = 56;
constexpr int OFF_W1H = 0;
constexpr int OFF_W1L = OFF_W1H + 48 * W1P * 2;    // 13056
constexpr int OFF_W2H = OFF_W1L + 48 * W1P * 2;    // 26112
constexpr int OFF_W2L = OFF_W2H + 128 * W2P * 2;   // 60928
constexpr int OFF_E   = OFF_W2L + 128 * W2P * 2;   // 95744; per-warp 16*EP*2 hi + lo
constexpr int EWBYTES = 16 * EP * 2;               // 1792 per half
constexpr int OFF_B1  = OFF_E + 8 * 2 * EWBYTES;   // 124416
constexpr int OFF_B2  = OFF_B1 + 512;
constexpr int MLP_SMEM = OFF_B2 + 512;             // 125440

__global__ __launch_bounds__(256, 1) void k_pairmlp_mma(
    const float* __restrict__ Wp1, const float* __restrict__ bp1,
    const float* __restrict__ Wp2, const float* __restrict__ bp2,
    float* __restrict__ out)
{
    extern __shared__ char sm[];
    uint32_t sb = s2u(sm);
    int tid = threadIdx.x, lane = tid & 31, w = tid >> 5;

    // stage weights (hi/lo split) once
    for (int idx = tid; idx < 48 * 128; idx += 256) {
        int k = idx >> 7, n = idx & 127;
        float v = (k < 36) ? Wp1[k * 128 + n] : 0.f;
        split1(v, ((__nv_bfloat16*)(sm + OFF_W1H))[k * W1P + n],
                  ((__nv_bfloat16*)(sm + OFF_W1L))[k * W1P + n]);
    }
    for (int idx = tid; idx < 128 * 128; idx += 256) {
        int k = idx >> 7, n = idx & 127;
        split1(Wp2[idx], ((__nv_bfloat16*)(sm + OFF_W2H))[k * W2P + n],
                         ((__nv_bfloat16*)(sm + OFF_W2L))[k * W2P + n]);
    }
    if (tid < 128) {
        ((float*)(sm + OFF_B1))[tid] = bp1[tid];
        ((float*)(sm + OFF_B2))[tid] = bp2[tid];
    }
    // zero E pad cols 36..47 in this warp's region
    {
        char* eh = sm + OFF_E + w * 2 * EWBYTES;
        char* el = eh + EWBYTES;
        for (int idx = lane; idx < 16 * 12; idx += 32) {
            int r = idx / 12, c = 36 + idx % 12;
            ((__nv_bfloat16*)eh)[r * EP + c] = __float2bfloat16_rn(0.f);
            ((__nv_bfloat16*)el)[r * EP + c] = __float2bfloat16_rn(0.f);
        }
    }
    __syncthreads();   // weights visible; after this, no block-wide syncs

    uint32_t ehBase = sb + OFF_E + w * 2 * EWBYTES;
    uint32_t elBase = ehBase + EWBYTES;
    uint32_t aAoff = (lane & 15) * (EP * 2) + (lane >> 4) * 16;
    int brow = (lane & 7) + ((lane >> 3) & 1) * 8, bc8 = (lane >> 4) * 8;
    uint32_t aBoff1 = brow * (W1P * 2) + bc8 * 2;
    uint32_t aBoff2 = brow * (W2P * 2) + bc8 * 2;
    const float* b1 = (const float*)(sm + OFF_B1);
    const float* b2 = (const float*)(sm + OFF_B2);

    for (int t = blockIdx.x; t < 4608; t += gridDim.x) {
        // stage this warp's 16 E rows (hi/lo split)
        {
            int i = t / 6, j0 = (t % 6) * 128 + w * 16;
            const float* src = g_edge + ((size_t)i * 36) * NRES + j0;
            __nv_bfloat16* eh = (__nv_bfloat16*)(sm + OFF_E + w * 2 * EWBYTES);
            __nv_bfloat16* el = eh + 16 * EP;
            for (int idx = lane; idx < 576; idx += 32) {
                int c = idx >> 4, jj = idx & 15;
                float v = src[(size_t)c * NRES + jj];
                split1(v, eh[jj * EP + c], el[jj * EP + c]);
            }
            __syncwarp();
        }

        // ---- layer 1: 16 rows x 128 hidden, K=48 ----
        float acc[16][4];
#pragma unroll
        for (int n = 0; n < 16; n++) {
            float2 bb = *(const float2*)&b1[n * 8 + (lane & 3) * 2];
            acc[n][0] = bb.x; acc[n][1] = bb.y; acc[n][2] = bb.x; acc[n][3] = bb.y;
        }
#pragma unroll
        for (int ks = 0; ks < 3; ks++) {
            uint32_t ah[4], al[4];
            ldm4(ah, ehBase + aAoff + ks * 32);
            ldm4(al, elBase + aAoff + ks * 32);
#pragma unroll
            for (int n = 0; n < 8; n++) {
                uint32_t bh[4], bl[4];
                ldm4t(bh, sb + OFF_W1H + ks * 16 * (W1P * 2) + aBoff1 + n * 32);
                ldm4t(bl, sb + OFF_W1L + ks * 16 * (W1P * 2) + aBoff1 + n * 32);
                mma_bf16(acc[2 * n], ah, bh[0], bh[1]);
                mma_bf16(acc[2 * n], ah, bl[0], bl[1]);
                mma_bf16(acc[2 * n], al, bh[0], bh[1]);
                mma_bf16(acc[2 * n + 1], ah, bh[2], bh[3]);
                mma_bf16(acc[2 * n + 1], ah, bl[2], bl[3]);
                mma_bf16(acc[2 * n + 1], al, bh[2], bh[3]);
            }
        }

        // gelu + split -> layer2 A fragments, entirely in registers.
        // acc step 2kc covers H cols kc*16+0..7, step 2kc+1 cols kc*16+8..15.
        // A-frag (m16k16): a0=(r,klo) a1=(r+8,klo) a2=(r,khi) a3=(r+8,khi)
        uint32_t afH[8][4], afL[8][4];
#pragma unroll
        for (int kc = 0; kc < 8; kc++) {
            float g0 = gelu_exact(acc[2 * kc][0]),     g1 = gelu_exact(acc[2 * kc][1]);
            float g2 = gelu_exact(acc[2 * kc][2]),     g3 = gelu_exact(acc[2 * kc][3]);
            float g4 = gelu_exact(acc[2 * kc + 1][0]), g5 = gelu_exact(acc[2 * kc + 1][1]);
            float g6 = gelu_exact(acc[2 * kc + 1][2]), g7 = gelu_exact(acc[2 * kc + 1][3]);
            split2(g0, g1, afH[kc][0], afL[kc][0]);
            split2(g2, g3, afH[kc][1], afL[kc][1]);
            split2(g4, g5, afH[kc][2], afL[kc][2]);
            split2(g6, g7, afH[kc][3], afL[kc][3]);
        }

        // ---- layer 2: out = H @ W2 + b2, K=128 ----
#pragma unroll
        for (int n = 0; n < 16; n++) {
            float2 bb = *(const float2*)&b2[n * 8 + (lane & 3) * 2];
            acc[n][0] = bb.x; acc[n][1] = bb.y; acc[n][2] = bb.x; acc[n][3] = bb.y;
        }
#pragma unroll
        for (int ks = 0; ks < 8; ks++) {
#pragma unroll
            for (int n = 0; n < 8; n++) {
                uint32_t bh[4], bl[4];
                ldm4t(bh, sb + OFF_W2H + ks * 16 * (W2P * 2) + aBoff2 + n * 32);
                ldm4t(bl, sb + OFF_W2L + ks * 16 * (W2P * 2) + aBoff2 + n * 32);
                mma_bf16(acc[2 * n], afH[ks], bh[0], bh[1]);
                mma_bf16(acc[2 * n], afH[ks], bl[0], bl[1]);
                mma_bf16(acc[2 * n], afL[ks], bh[0], bh[1]);
                mma_bf16(acc[2 * n + 1], afH[ks], bh[2], bh[3]);
                mma_bf16(acc[2 * n + 1], afH[ks], bl[2], bl[3]);
                mma_bf16(acc[2 * n + 1], afL[ks], bh[2], bh[3]);
            }
        }
        {
            float* dst = out + (size_t)t * 128 * 128;
            int rlo = w * 16 + (lane >> 2);
#pragma unroll
            for (int n = 0; n < 16; n++) {
                int c = n * 8 + (lane & 3) * 2;
                *(float2*)&dst[(size_t)rlo * 128 + c] = make_float2(acc[n][0], acc[n][1]);
                *(float2*)&dst[(size_t)(rlo + 8) * 128 + c] = make_float2(acc[n][2], acc[n][3]);
            }
        }
    }
}

// ---------------- host launcher ----------------
extern "C" void kernel_launch(void* const* d_in, const int* in_sizes, int n_in,
                              void* d_out, int out_size) {
    const float* scalar = (const float*)d_in[0];
    const float* pair   = (const float*)d_in[1];
    const float* rot    = (const float*)d_in[2];
    const float* trans  = (const float*)d_in[3];
    // d_in[4] = mask (all true; no-op)
    const float* Wqkv = (const float*)d_in[5];
    const float* Wpb  = (const float*)d_in[6];
    const float* pw   = (const float*)d_in[7];
    const float* Wout = (const float*)d_in[8];
    const float* bout = (const float*)d_in[9];
    const float* Wp1  = (const float*)d_in[10];
    const float* bp1  = (const float*)d_in[11];
    const float* Wp2  = (const float*)d_in[12];
    const float* bp2  = (const float*)d_in[13];
    float* out = (float*)d_out;

    cudaFuncSetAttribute(k_pairmlp_mma, cudaFuncAttributeMaxDynamicSharedMemorySize, MLP_SMEM);

    float* g_qkv_p;   cudaGetSymbolAddress((void**)&g_qkv_p, g_qkv);
    float* g_feats_p; cudaGetSymbolAddress((void**)&g_feats_p, g_feats);

    gemm_mma3<<<dim3(DQKV / 128, NRES / 128), 256>>>(scalar, Wqkv, g_qkv_p, NRES, DQKV, DSC, nullptr);
    k_points<<<NRES, 192>>>(rot, trans);
    k_pairbias<<<NRES * 3, 256>>>(pair, Wpb);
    k_qk<<<dim3(NRES / 64, NRES / 64, NH), 256>>>(pw);
    k_softmax2<<<NRES, 256>>>();
    k_respair<<<NRES, 128>>>(pair);
    k_resv<<<dim3(NRES / 64, NH), 256>>>();
    k_local<<<NRES, 96>>>(rot, trans);
    gemm_mma3<<<dim3(DSC / 128, NRES / 128), 256>>>(g_feats_p, Wout, out, NRES, DSC, DOUT, bout);
    k_pairmlp_mma<<<148, 256, MLP_SMEM>>>(Wp1, bp1, Wp2, bp2, out + NRES * DSC);
}